// round 1
// baseline (speedup 1.0000x reference)
#include <cuda_runtime.h>
#include <math.h>

#define BATCH 16
#define SEQ   512
#define DIM   2048
#define NH    16
#define NG    4
#define HD    128
#define MROWS (BATCH*SEQ)   // 8192

// scratch (device globals — no allocation allowed)
__device__ float g_q[(size_t)MROWS * DIM];          // (b,s,H,hd)
__device__ float g_k[(size_t)MROWS * NG * HD];      // (b,s,G,hd)
__device__ float g_v[(size_t)MROWS * NG * HD];      // (b,s,G,hd)
__device__ float g_ao[(size_t)MROWS * DIM];         // attention output (b,s,H,hd)

// ---------------------------------------------------------------------------
// SGEMM: C = A(MxK) * B(KxN) + bias   (all row-major), 128x128 tile, BK=8
// ---------------------------------------------------------------------------
__global__ __launch_bounds__(256) void sgemm_bias(
    const float* __restrict__ A, const float* __restrict__ Bm,
    const float* __restrict__ bias, float* __restrict__ C,
    int Mdim, int N, int K)
{
    __shared__ float As[8][128];
    __shared__ float Bs[8][128];

    int tid = threadIdx.x;
    int bx = blockIdx.x * 128;
    int by = blockIdx.y * 128;
    int tx = (tid & 15) * 8;
    int ty = (tid >> 4) * 8;

    int arow = tid >> 1, acol = (tid & 1) * 4;   // A tile: 128 rows x 8 cols
    int brow = tid >> 5, bcol = (tid & 31) * 4;  // B tile: 8 rows x 128 cols

    const float* Ap = A + (size_t)(by + arow) * K + acol;
    const float* Bp = Bm + (size_t)brow * N + bx + bcol;

    float acc[8][8];
    #pragma unroll
    for (int i = 0; i < 8; i++)
        #pragma unroll
        for (int j = 0; j < 8; j++) acc[i][j] = 0.f;

    for (int k0 = 0; k0 < K; k0 += 8) {
        float4 av = *(const float4*)(Ap + k0);
        As[acol + 0][arow] = av.x;
        As[acol + 1][arow] = av.y;
        As[acol + 2][arow] = av.z;
        As[acol + 3][arow] = av.w;
        *(float4*)&Bs[brow][bcol] = *(const float4*)(Bp + (size_t)k0 * N);
        __syncthreads();

        #pragma unroll
        for (int kk = 0; kk < 8; kk++) {
            float ar[8], br[8];
            *(float4*)(ar)     = *(float4*)&As[kk][ty];
            *(float4*)(ar + 4) = *(float4*)&As[kk][ty + 4];
            *(float4*)(br)     = *(float4*)&Bs[kk][tx];
            *(float4*)(br + 4) = *(float4*)&Bs[kk][tx + 4];
            #pragma unroll
            for (int i = 0; i < 8; i++)
                #pragma unroll
                for (int j = 0; j < 8; j++)
                    acc[i][j] += ar[i] * br[j];
        }
        __syncthreads();
    }

    float bvals[8];
    #pragma unroll
    for (int j = 0; j < 8; j++) bvals[j] = bias[bx + tx + j];

    #pragma unroll
    for (int i = 0; i < 8; i++) {
        float* Cp = C + (size_t)(by + ty + i) * N + bx + tx;
        float4 o0 = make_float4(acc[i][0] + bvals[0], acc[i][1] + bvals[1],
                                acc[i][2] + bvals[2], acc[i][3] + bvals[3]);
        float4 o1 = make_float4(acc[i][4] + bvals[4], acc[i][5] + bvals[5],
                                acc[i][6] + bvals[6], acc[i][7] + bvals[7]);
        *(float4*)(Cp)     = o0;
        *(float4*)(Cp + 4) = o1;
    }
}

// ---------------------------------------------------------------------------
// Fused RMSNorm + RoPE over (token, head) rows of hd=128.
// extra_scale folds the q attention scaling (1/hd total for q, 1 for k).
// ---------------------------------------------------------------------------
__global__ __launch_bounds__(64) void norm_rope(
    float* __restrict__ buf, const float* __restrict__ scale,
    int nheads, float extra_scale)
{
    int row = blockIdx.x;          // 0 .. MROWS-1
    int h   = blockIdx.y;
    int pos = row & (SEQ - 1);     // position within sequence
    float* p = buf + ((size_t)row * nheads + h) * HD;

    int i = threadIdx.x;           // 0..63, handles pair (2i, 2i+1)
    float2 xv = *(float2*)&p[2 * i];

    float ss = xv.x * xv.x + xv.y * xv.y;
    #pragma unroll
    for (int off = 16; off; off >>= 1)
        ss += __shfl_xor_sync(0xffffffffu, ss, off);
    __shared__ float sw[2];
    if ((threadIdx.x & 31) == 0) sw[threadIdx.x >> 5] = ss;
    __syncthreads();
    float total = sw[0] + sw[1];
    float rinv = rsqrtf(total * (1.0f / HD) + 1e-6f);

    float x1 = xv.x * rinv * scale[2 * i];
    float x2 = xv.y * rinv * scale[2 * i + 1];

    // inv_freq[i] = 10000^(-i/64)
    float inv_freq = expf(-(float)i * (9.210340371976184f / 64.0f));
    float fr = (float)pos * inv_freq;
    float sn = sinf(fr), cs = cosf(fr);

    float o1 = (x1 * cs - x2 * sn) * extra_scale;
    float o2 = (x1 * sn + x2 * cs) * extra_scale;
    p[2 * i]     = o1;
    p[2 * i + 1] = o2;
}

// ---------------------------------------------------------------------------
// fp32 flash attention. grid (SEQ/32, NH, BATCH), 128 threads.
// q already carries the full 1/hd scaling. Causal.
// ---------------------------------------------------------------------------
__global__ __launch_bounds__(128) void flash_attn(
    const float* __restrict__ q, const float* __restrict__ k,
    const float* __restrict__ v, float* __restrict__ o)
{
    constexpr int BR = 32, BC = 32;
    __shared__ float QsT[HD * 33];   // transposed Q, stride 33 (scalar reads)
    __shared__ float KV[HD * 36];    // union: KsT stride 36 / Vs row-major [32][128]
    __shared__ float Ps[BR * 36];    // P tile, stride 36

    int qb = blockIdx.x, h = blockIdx.y, b = blockIdx.z;
    int g = h >> 2;
    int tid = threadIdx.x;
    int tx = tid & 7;       // 0..7
    int ty = tid >> 3;      // 0..15 -> rows 2ty, 2ty+1

    // load Q tile transposed
    for (int i = tid; i < BR * HD / 4; i += 128) {
        int r = i >> 5, c4 = i & 31;
        float4 t = *(const float4*)&q[(((size_t)(b * SEQ + qb * BR + r)) * NH + h) * HD + c4 * 4];
        QsT[(c4 * 4 + 0) * 33 + r] = t.x;
        QsT[(c4 * 4 + 1) * 33 + r] = t.y;
        QsT[(c4 * 4 + 2) * 33 + r] = t.z;
        QsT[(c4 * 4 + 3) * 33 + r] = t.w;
    }

    float o0[16], o1[16];
    #pragma unroll
    for (int j = 0; j < 16; j++) { o0[j] = 0.f; o1[j] = 0.f; }
    float m0 = -1e30f, m1 = -1e30f, l0 = 0.f, l1 = 0.f;
    int qi0 = qb * BR + 2 * ty, qi1 = qi0 + 1;

    for (int kt = 0; kt <= qb; kt++) {
        __syncthreads();  // Q ready (first iter) / prev P·V done

        // load K tile transposed (stride 36)
        for (int i = tid; i < BC * HD / 4; i += 128) {
            int r = i >> 5, c4 = i & 31;
            float4 t = *(const float4*)&k[(((size_t)(b * SEQ + kt * BC + r)) * NG + g) * HD + c4 * 4];
            KV[(c4 * 4 + 0) * 36 + r] = t.x;
            KV[(c4 * 4 + 1) * 36 + r] = t.y;
            KV[(c4 * 4 + 2) * 36 + r] = t.z;
            KV[(c4 * 4 + 3) * 36 + r] = t.w;
        }
        __syncthreads();

        // S = Q K^T for this thread's 2 rows x 4 cols (cols = tx*4 + j)
        float s0[4] = {0, 0, 0, 0}, s1[4] = {0, 0, 0, 0};
        #pragma unroll 4
        for (int kk = 0; kk < HD; kk++) {
            float a0 = QsT[kk * 33 + 2 * ty];
            float a1 = QsT[kk * 33 + 2 * ty + 1];
            float4 bv = *(const float4*)&KV[kk * 36 + tx * 4];
            s0[0] += a0 * bv.x; s0[1] += a0 * bv.y; s0[2] += a0 * bv.z; s0[3] += a0 * bv.w;
            s1[0] += a1 * bv.x; s1[1] += a1 * bv.y; s1[2] += a1 * bv.z; s1[3] += a1 * bv.w;
        }

        // causal mask on diagonal tile
        if (kt == qb) {
            #pragma unroll
            for (int j = 0; j < 4; j++) {
                int kj = kt * BC + tx * 4 + j;
                if (kj > qi0) s0[j] = -1e30f;
                if (kj > qi1) s1[j] = -1e30f;
            }
        }

        // online softmax: row reductions across the 8-lane tx group
        float mt0 = fmaxf(fmaxf(s0[0], s0[1]), fmaxf(s0[2], s0[3]));
        float mt1 = fmaxf(fmaxf(s1[0], s1[1]), fmaxf(s1[2], s1[3]));
        #pragma unroll
        for (int off = 4; off; off >>= 1) {
            mt0 = fmaxf(mt0, __shfl_xor_sync(0xffffffffu, mt0, off));
            mt1 = fmaxf(mt1, __shfl_xor_sync(0xffffffffu, mt1, off));
        }
        float mn0 = fmaxf(m0, mt0), mn1 = fmaxf(m1, mt1);

        float p0[4], p1[4];
        float su0 = 0.f, su1 = 0.f;
        #pragma unroll
        for (int j = 0; j < 4; j++) {
            p0[j] = expf(s0[j] - mn0); su0 += p0[j];
            p1[j] = expf(s1[j] - mn1); su1 += p1[j];
        }
        #pragma unroll
        for (int off = 4; off; off >>= 1) {
            su0 += __shfl_xor_sync(0xffffffffu, su0, off);
            su1 += __shfl_xor_sync(0xffffffffu, su1, off);
        }
        float al0 = expf(m0 - mn0), al1 = expf(m1 - mn1);
        l0 = l0 * al0 + su0;
        l1 = l1 * al1 + su1;
        m0 = mn0; m1 = mn1;
        #pragma unroll
        for (int j = 0; j < 16; j++) { o0[j] *= al0; o1[j] *= al1; }

        *(float4*)&Ps[(2 * ty) * 36 + tx * 4]     = make_float4(p0[0], p0[1], p0[2], p0[3]);
        *(float4*)&Ps[(2 * ty + 1) * 36 + tx * 4] = make_float4(p1[0], p1[1], p1[2], p1[3]);
        __syncthreads();  // P visible; KsT reads done

        // load V tile row-major (overwrites KV)
        for (int i = tid; i < BC * HD / 4; i += 128) {
            int r = i >> 5, c4 = i & 31;
            *(float4*)&KV[r * 128 + c4 * 4] =
                *(const float4*)&v[(((size_t)(b * SEQ + kt * BC + r)) * NG + g) * HD + c4 * 4];
        }
        __syncthreads();

        // O += P V : this thread's cols = jj*32 + tx*4 + qq (reg jj*4+qq)
        for (int c = 0; c < BC; c++) {
            float pa = Ps[(2 * ty) * 36 + c];
            float pb = Ps[(2 * ty + 1) * 36 + c];
            #pragma unroll
            for (int jj = 0; jj < 4; jj++) {
                float4 vv = *(const float4*)&KV[c * 128 + jj * 32 + tx * 4];
                o0[jj * 4 + 0] += pa * vv.x; o0[jj * 4 + 1] += pa * vv.y;
                o0[jj * 4 + 2] += pa * vv.z; o0[jj * 4 + 3] += pa * vv.w;
                o1[jj * 4 + 0] += pb * vv.x; o1[jj * 4 + 1] += pb * vv.y;
                o1[jj * 4 + 2] += pb * vv.z; o1[jj * 4 + 3] += pb * vv.w;
            }
        }
    }

    float rl0 = 1.0f / l0, rl1 = 1.0f / l1;
    size_t base0 = (((size_t)(b * SEQ + qi0)) * NH + h) * HD;
    size_t base1 = (((size_t)(b * SEQ + qi1)) * NH + h) * HD;
    #pragma unroll
    for (int jj = 0; jj < 4; jj++) {
        float4 w0 = make_float4(o0[jj * 4 + 0] * rl0, o0[jj * 4 + 1] * rl0,
                                o0[jj * 4 + 2] * rl0, o0[jj * 4 + 3] * rl0);
        float4 w1 = make_float4(o1[jj * 4 + 0] * rl1, o1[jj * 4 + 1] * rl1,
                                o1[jj * 4 + 2] * rl1, o1[jj * 4 + 3] * rl1);
        *(float4*)&o[base0 + jj * 32 + tx * 4] = w0;
        *(float4*)&o[base1 + jj * 32 + tx * 4] = w1;
    }
}

// ---------------------------------------------------------------------------
extern "C" void kernel_launch(void* const* d_in, const int* in_sizes, int n_in,
                              void* d_out, int out_size)
{
    const float* x   = (const float*)d_in[0];
    const float* Wq  = (const float*)d_in[1];
    const float* bq  = (const float*)d_in[2];
    const float* Wk  = (const float*)d_in[3];
    const float* bk  = (const float*)d_in[4];
    const float* Wv  = (const float*)d_in[5];
    const float* bv  = (const float*)d_in[6];
    const float* Wo  = (const float*)d_in[7];
    const float* bo  = (const float*)d_in[8];
    const float* qns = (const float*)d_in[9];
    const float* kns = (const float*)d_in[10];
    float* out = (float*)d_out;

    float *q_buf, *k_buf, *v_buf, *ao_buf;
    cudaGetSymbolAddress((void**)&q_buf,  g_q);
    cudaGetSymbolAddress((void**)&k_buf,  g_k);
    cudaGetSymbolAddress((void**)&v_buf,  g_v);
    cudaGetSymbolAddress((void**)&ao_buf, g_ao);

    const int KVD = NG * HD;  // 512

    // projections
    sgemm_bias<<<dim3(DIM / 128, MROWS / 128), 256>>>(x, Wq, bq, q_buf, MROWS, DIM, DIM);
    sgemm_bias<<<dim3(KVD / 128, MROWS / 128), 256>>>(x, Wk, bk, k_buf, MROWS, KVD, DIM);
    sgemm_bias<<<dim3(KVD / 128, MROWS / 128), 256>>>(x, Wv, bv, v_buf, MROWS, KVD, DIM);

    // rmsnorm + rope (q gets full 1/hd logit scaling folded in)
    norm_rope<<<dim3(MROWS, NH), 64>>>(q_buf, qns, NH, 1.0f / (float)HD);
    norm_rope<<<dim3(MROWS, NG), 64>>>(k_buf, kns, NG, 1.0f);

    // attention
    flash_attn<<<dim3(SEQ / 32, NH, BATCH), 128>>>(q_buf, k_buf, v_buf, ao_buf);

    // output projection
    sgemm_bias<<<dim3(DIM / 128, MROWS / 128), 256>>>(ao_buf, Wo, bo, out, MROWS, DIM, DIM);
}

// round 3
// speedup vs baseline: 2.1635x; 2.1635x over previous
#include <cuda_runtime.h>
#include <cuda_fp16.h>
#include <cstdint>
#include <math.h>

#define BATCH 16
#define SEQ   512
#define DIM   2048
#define NH    16
#define NG    4
#define HD    128
#define MROWS (BATCH*SEQ)   // 8192
#define KVD   (NG*HD)       // 512

// ---------------------------------------------------------------------------
// scratch (device globals — no allocation allowed)
// ---------------------------------------------------------------------------
__device__ float g_q[(size_t)MROWS * DIM];
__device__ float g_k[(size_t)MROWS * KVD];
__device__ float g_v[(size_t)MROWS * KVD];
__device__ float g_ao[(size_t)MROWS * DIM];

__device__ __half g_xhi[(size_t)MROWS * DIM];
__device__ __half g_xlo[(size_t)MROWS * DIM];
__device__ __half g_aohi[(size_t)MROWS * DIM];
__device__ __half g_aolo[(size_t)MROWS * DIM];
__device__ __half g_wqh[(size_t)DIM * DIM];
__device__ __half g_wql[(size_t)DIM * DIM];
__device__ __half g_woh[(size_t)DIM * DIM];
__device__ __half g_wol[(size_t)DIM * DIM];
__device__ __half g_wkh[(size_t)KVD * DIM];
__device__ __half g_wkl[(size_t)KVD * DIM];
__device__ __half g_wvh[(size_t)KVD * DIM];
__device__ __half g_wvl[(size_t)KVD * DIM];

// ---------------------------------------------------------------------------
// helpers
// ---------------------------------------------------------------------------
__device__ __forceinline__ uint32_t smem_to_u32(const void* p) {
    uint32_t a;
    asm("{ .reg .u64 t; cvta.to.shared.u64 t, %1; cvt.u32.u64 %0, t; }" : "=r"(a) : "l"(p));
    return a;
}
#define SMEM_SWIZZLE_128B(bo) ((bo) ^ (((bo) >> 3) & 0x70))

__device__ __forceinline__ void cp16(uint32_t s, const void* g) {
    asm volatile("cp.async.cg.shared.global [%0], [%1], 16;" :: "r"(s), "l"(g) : "memory");
}
__device__ __forceinline__ void ldm4(uint32_t* r, uint32_t a) {
    asm volatile("ldmatrix.sync.aligned.m8n8.x4.shared.b16 {%0,%1,%2,%3}, [%4];"
                 : "=r"(r[0]), "=r"(r[1]), "=r"(r[2]), "=r"(r[3]) : "r"(a));
}
__device__ __forceinline__ void mma16816(float* d, const uint32_t* a, const uint32_t* b) {
    asm volatile(
        "mma.sync.aligned.m16n8k16.row.col.f32.f16.f16.f32 "
        "{%0,%1,%2,%3},{%4,%5,%6,%7},{%8,%9},{%0,%1,%2,%3};"
        : "+f"(d[0]), "+f"(d[1]), "+f"(d[2]), "+f"(d[3])
        : "r"(a[0]), "r"(a[1]), "r"(a[2]), "r"(a[3]), "r"(b[0]), "r"(b[1]));
}
__device__ __forceinline__ uint32_t pk2h(float a, float b) {
    __half2 h = __floats2half2_rn(a, b);
    return *reinterpret_cast<uint32_t*>(&h);
}

// ---------------------------------------------------------------------------
// convert fp32 -> fp16 hi + fp16 lo (residual)
// ---------------------------------------------------------------------------
__global__ __launch_bounds__(256) void convert_split(
    const float* __restrict__ in, __half* __restrict__ hi,
    __half* __restrict__ lo, int n4)
{
    int i = blockIdx.x * 256 + threadIdx.x;
    if (i >= n4) return;
    float4 v = ((const float4*)in)[i];
    float hx = __half2float(__float2half_rn(v.x));
    float hy = __half2float(__float2half_rn(v.y));
    float hz = __half2float(__float2half_rn(v.z));
    float hw = __half2float(__float2half_rn(v.w));
    uint2 ph, pl;
    ph.x = pk2h(v.x, v.y); ph.y = pk2h(v.z, v.w);
    pl.x = pk2h(v.x - hx, v.y - hy); pl.y = pk2h(v.z - hz, v.w - hw);
    ((uint2*)hi)[i] = ph;
    ((uint2*)lo)[i] = pl;
}

// ---------------------------------------------------------------------------
// W [K, N] fp32 -> W^T [N, K] fp16 hi/lo
// ---------------------------------------------------------------------------
__global__ __launch_bounds__(256) void transpose_split(
    const float* __restrict__ W, __half* __restrict__ Th,
    __half* __restrict__ Tl, int K, int N)
{
    __shared__ float tile[32][33];
    int n0 = blockIdx.x * 32, k0 = blockIdx.y * 32;
    int tx = threadIdx.x, ty = threadIdx.y;   // 32 x 8
    #pragma unroll
    for (int j = ty; j < 32; j += 8)
        tile[j][tx] = W[(size_t)(k0 + j) * N + n0 + tx];
    __syncthreads();
    #pragma unroll
    for (int j = ty; j < 32; j += 8) {
        float v = tile[tx][j];   // = W[k0+tx][n0+j]
        __half h = __float2half_rn(v);
        float r = v - __half2float(h);
        size_t o = (size_t)(n0 + j) * K + k0 + tx;
        Th[o] = h;
        Tl[o] = __float2half_rn(r);
    }
}

// ---------------------------------------------------------------------------
// HMMA split-3 fp16 GEMM: C[M,N] = A[M,K=2048] * W[K,N] + bias
//   A hi/lo fp16 [M,K] row-major; W hi/lo fp16 [N,K] row-major (W^T).
//   CTA tile 128x128, BK=64, cp.async double buffer, 8 warps (2x4).
// ---------------------------------------------------------------------------
#define BM 128
#define BN 128
#define BK 64
#define NCH (DIM / BK)   // 32
#define STG_BYTES 65536
#define OFF_AH 0
#define OFF_AL 16384
#define OFF_BH 32768
#define OFF_BL 49152
#define GEMM_SMEM (2 * STG_BYTES)   // 131072

__global__ __launch_bounds__(256, 1) void gemm_hmma(
    const __half* __restrict__ Ahg, const __half* __restrict__ Alg,
    const __half* __restrict__ Bhg, const __half* __restrict__ Blg,
    const float* __restrict__ bias, float* __restrict__ C, int N)
{
    extern __shared__ char sm[];
    uint32_t sb = smem_to_u32(sm);
    int tid = threadIdx.x, lane = tid & 31, wid = tid >> 5;
    int wm = wid & 1, wn = wid >> 1;          // warp tile: 64(M) x 32(N)
    int bx = blockIdx.x * BN, by = blockIdx.y * BM;

    auto load_stage = [&](int s, int kt) {
        int k0 = kt * BK;
        uint32_t base = sb + s * STG_BYTES;
        #pragma unroll
        for (int t = 0; t < 4; t++) {
            int idx = tid + t * 256;
            int r = idx >> 3, c16 = idx & 7;
            uint32_t swz = SMEM_SWIZZLE_128B((uint32_t)(r * 128 + c16 * 16));
            size_t ga = (size_t)(by + r) * DIM + k0 + c16 * 8;
            size_t gb = (size_t)(bx + r) * DIM + k0 + c16 * 8;
            cp16(base + OFF_AH + swz, Ahg + ga);
            cp16(base + OFF_AL + swz, Alg + ga);
            cp16(base + OFF_BH + swz, Bhg + gb);
            cp16(base + OFF_BL + swz, Blg + gb);
        }
    };

    float d[4][4][4];
    #pragma unroll
    for (int i = 0; i < 4; i++)
        #pragma unroll
        for (int j = 0; j < 4; j++)
            #pragma unroll
            for (int q = 0; q < 4; q++) d[i][j][q] = 0.f;

    load_stage(0, 0);
    asm volatile("cp.async.commit_group;" ::: "memory");
    load_stage(1, 1);
    asm volatile("cp.async.commit_group;" ::: "memory");

    for (int kt = 0; kt < NCH; kt++) {
        if (kt < NCH - 1) asm volatile("cp.async.wait_group 1;" ::: "memory");
        else              asm volatile("cp.async.wait_group 0;" ::: "memory");
        __syncthreads();

        int s = kt & 1;
        uint32_t base = sb + s * STG_BYTES;

        // fragment address components
        int arow = wm * 64 + (lane & 15);
        int bro  = wn * 32 + (lane & 7) + ((lane >> 4) << 3);
        int bkh  = ((lane >> 3) & 1) << 3;

        #pragma unroll
        for (int ks = 0; ks < 4; ks++) {
            int acol = ks * 16 + ((lane >> 4) << 3);
            uint32_t ah[4][4], al[4][4], bh[4][2], bl[4][2];
            #pragma unroll
            for (int mf = 0; mf < 4; mf++) {
                uint32_t off = SMEM_SWIZZLE_128B(
                    (uint32_t)((arow + mf * 16) * 128 + acol * 2));
                ldm4(ah[mf], base + OFF_AH + off);
                ldm4(al[mf], base + OFF_AL + off);
            }
            #pragma unroll
            for (int j2 = 0; j2 < 2; j2++) {
                uint32_t off = SMEM_SWIZZLE_128B(
                    (uint32_t)((bro + j2 * 16) * 128 + (ks * 16 + bkh) * 2));
                uint32_t r[4];
                ldm4(r, base + OFF_BH + off);
                bh[j2 * 2][0] = r[0]; bh[j2 * 2][1] = r[1];
                bh[j2 * 2 + 1][0] = r[2]; bh[j2 * 2 + 1][1] = r[3];
                ldm4(r, base + OFF_BL + off);
                bl[j2 * 2][0] = r[0]; bl[j2 * 2][1] = r[1];
                bl[j2 * 2 + 1][0] = r[2]; bl[j2 * 2 + 1][1] = r[3];
            }
            #pragma unroll
            for (int mf = 0; mf < 4; mf++)
                #pragma unroll
                for (int nf = 0; nf < 4; nf++) {
                    mma16816(d[mf][nf], ah[mf], bh[nf]);
                    mma16816(d[mf][nf], ah[mf], bl[nf]);
                    mma16816(d[mf][nf], al[mf], bh[nf]);
                }
        }
        __syncthreads();

        if (kt + 2 < NCH) {
            load_stage(s, kt + 2);
            asm volatile("cp.async.commit_group;" ::: "memory");
        }
    }

    // epilogue: d-frag lane mapping: c0,c1 -> (row l/4, col 2(l%4)+{0,1}); c2,c3 -> row+8
    int row0 = by + wm * 64 + (lane >> 2);
    int col0 = bx + wn * 32 + (lane & 3) * 2;
    #pragma unroll
    for (int mf = 0; mf < 4; mf++)
        #pragma unroll
        for (int nf = 0; nf < 4; nf++) {
            int r = row0 + mf * 16;
            int c = col0 + nf * 8;
            float b0 = bias[c], b1 = bias[c + 1];
            float2 v0 = make_float2(d[mf][nf][0] + b0, d[mf][nf][1] + b1);
            float2 v1 = make_float2(d[mf][nf][2] + b0, d[mf][nf][3] + b1);
            *(float2*)&C[(size_t)r * N + c] = v0;
            *(float2*)&C[(size_t)(r + 8) * N + c] = v1;
        }
}

// ---------------------------------------------------------------------------
// Fused RMSNorm + RoPE
// ---------------------------------------------------------------------------
__global__ __launch_bounds__(64) void norm_rope(
    float* __restrict__ buf, const float* __restrict__ scale,
    int nheads, float extra_scale)
{
    int row = blockIdx.x;
    int h   = blockIdx.y;
    int pos = row & (SEQ - 1);
    float* p = buf + ((size_t)row * nheads + h) * HD;

    int i = threadIdx.x;
    float2 xv = *(float2*)&p[2 * i];

    float ss = xv.x * xv.x + xv.y * xv.y;
    #pragma unroll
    for (int off = 16; off; off >>= 1)
        ss += __shfl_xor_sync(0xffffffffu, ss, off);
    __shared__ float sw[2];
    if ((threadIdx.x & 31) == 0) sw[threadIdx.x >> 5] = ss;
    __syncthreads();
    float total = sw[0] + sw[1];
    float rinv = rsqrtf(total * (1.0f / HD) + 1e-6f);

    float x1 = xv.x * rinv * scale[2 * i];
    float x2 = xv.y * rinv * scale[2 * i + 1];

    float inv_freq = expf(-(float)i * (9.210340371976184f / 64.0f));
    float fr = (float)pos * inv_freq;
    float sn = sinf(fr), cs = cosf(fr);

    p[2 * i]     = (x1 * cs - x2 * sn) * extra_scale;
    p[2 * i + 1] = (x1 * sn + x2 * cs) * extra_scale;
}

// ---------------------------------------------------------------------------
// fp32 flash attention
// ---------------------------------------------------------------------------
__global__ __launch_bounds__(128) void flash_attn(
    const float* __restrict__ q, const float* __restrict__ k,
    const float* __restrict__ v, float* __restrict__ o)
{
    constexpr int BR = 32, BC = 32;
    __shared__ float QsT[HD * 33];
    __shared__ float KV[HD * 36];
    __shared__ float Ps[BR * 36];

    int qb = blockIdx.x, h = blockIdx.y, b = blockIdx.z;
    int g = h >> 2;
    int tid = threadIdx.x;
    int tx = tid & 7;
    int ty = tid >> 3;

    for (int i = tid; i < BR * HD / 4; i += 128) {
        int r = i >> 5, c4 = i & 31;
        float4 t = *(const float4*)&q[(((size_t)(b * SEQ + qb * BR + r)) * NH + h) * HD + c4 * 4];
        QsT[(c4 * 4 + 0) * 33 + r] = t.x;
        QsT[(c4 * 4 + 1) * 33 + r] = t.y;
        QsT[(c4 * 4 + 2) * 33 + r] = t.z;
        QsT[(c4 * 4 + 3) * 33 + r] = t.w;
    }

    float o0[16], o1[16];
    #pragma unroll
    for (int j = 0; j < 16; j++) { o0[j] = 0.f; o1[j] = 0.f; }
    float m0 = -1e30f, m1 = -1e30f, l0 = 0.f, l1 = 0.f;
    int qi0 = qb * BR + 2 * ty, qi1 = qi0 + 1;

    for (int kt = 0; kt <= qb; kt++) {
        __syncthreads();

        for (int i = tid; i < BC * HD / 4; i += 128) {
            int r = i >> 5, c4 = i & 31;
            float4 t = *(const float4*)&k[(((size_t)(b * SEQ + kt * BC + r)) * NG + g) * HD + c4 * 4];
            KV[(c4 * 4 + 0) * 36 + r] = t.x;
            KV[(c4 * 4 + 1) * 36 + r] = t.y;
            KV[(c4 * 4 + 2) * 36 + r] = t.z;
            KV[(c4 * 4 + 3) * 36 + r] = t.w;
        }
        __syncthreads();

        float s0[4] = {0, 0, 0, 0}, s1[4] = {0, 0, 0, 0};
        #pragma unroll 4
        for (int kk = 0; kk < HD; kk++) {
            float a0 = QsT[kk * 33 + 2 * ty];
            float a1 = QsT[kk * 33 + 2 * ty + 1];
            float4 bv = *(const float4*)&KV[kk * 36 + tx * 4];
            s0[0] += a0 * bv.x; s0[1] += a0 * bv.y; s0[2] += a0 * bv.z; s0[3] += a0 * bv.w;
            s1[0] += a1 * bv.x; s1[1] += a1 * bv.y; s1[2] += a1 * bv.z; s1[3] += a1 * bv.w;
        }

        if (kt == qb) {
            #pragma unroll
            for (int j = 0; j < 4; j++) {
                int kj = kt * BC + tx * 4 + j;
                if (kj > qi0) s0[j] = -1e30f;
                if (kj > qi1) s1[j] = -1e30f;
            }
        }

        float mt0 = fmaxf(fmaxf(s0[0], s0[1]), fmaxf(s0[2], s0[3]));
        float mt1 = fmaxf(fmaxf(s1[0], s1[1]), fmaxf(s1[2], s1[3]));
        #pragma unroll
        for (int off = 4; off; off >>= 1) {
            mt0 = fmaxf(mt0, __shfl_xor_sync(0xffffffffu, mt0, off));
            mt1 = fmaxf(mt1, __shfl_xor_sync(0xffffffffu, mt1, off));
        }
        float mn0 = fmaxf(m0, mt0), mn1 = fmaxf(m1, mt1);

        float p0[4], p1[4];
        float su0 = 0.f, su1 = 0.f;
        #pragma unroll
        for (int j = 0; j < 4; j++) {
            p0[j] = expf(s0[j] - mn0); su0 += p0[j];
            p1[j] = expf(s1[j] - mn1); su1 += p1[j];
        }
        #pragma unroll
        for (int off = 4; off; off >>= 1) {
            su0 += __shfl_xor_sync(0xffffffffu, su0, off);
            su1 += __shfl_xor_sync(0xffffffffu, su1, off);
        }
        float al0 = expf(m0 - mn0), al1 = expf(m1 - mn1);
        l0 = l0 * al0 + su0;
        l1 = l1 * al1 + su1;
        m0 = mn0; m1 = mn1;
        #pragma unroll
        for (int j = 0; j < 16; j++) { o0[j] *= al0; o1[j] *= al1; }

        *(float4*)&Ps[(2 * ty) * 36 + tx * 4]     = make_float4(p0[0], p0[1], p0[2], p0[3]);
        *(float4*)&Ps[(2 * ty + 1) * 36 + tx * 4] = make_float4(p1[0], p1[1], p1[2], p1[3]);
        __syncthreads();

        for (int i = tid; i < BC * HD / 4; i += 128) {
            int r = i >> 5, c4 = i & 31;
            *(float4*)&KV[r * 128 + c4 * 4] =
                *(const float4*)&v[(((size_t)(b * SEQ + kt * BC + r)) * NG + g) * HD + c4 * 4];
        }
        __syncthreads();

        for (int c = 0; c < BC; c++) {
            float pa = Ps[(2 * ty) * 36 + c];
            float pb = Ps[(2 * ty + 1) * 36 + c];
            #pragma unroll
            for (int jj = 0; jj < 4; jj++) {
                float4 vv = *(const float4*)&KV[c * 128 + jj * 32 + tx * 4];
                o0[jj * 4 + 0] += pa * vv.x; o0[jj * 4 + 1] += pa * vv.y;
                o0[jj * 4 + 2] += pa * vv.z; o0[jj * 4 + 3] += pa * vv.w;
                o1[jj * 4 + 0] += pb * vv.x; o1[jj * 4 + 1] += pb * vv.y;
                o1[jj * 4 + 2] += pb * vv.z; o1[jj * 4 + 3] += pb * vv.w;
            }
        }
    }

    float rl0 = 1.0f / l0, rl1 = 1.0f / l1;
    size_t base0 = (((size_t)(b * SEQ + qi0)) * NH + h) * HD;
    size_t base1 = (((size_t)(b * SEQ + qi1)) * NH + h) * HD;
    #pragma unroll
    for (int jj = 0; jj < 4; jj++) {
        float4 w0 = make_float4(o0[jj * 4 + 0] * rl0, o0[jj * 4 + 1] * rl0,
                                o0[jj * 4 + 2] * rl0, o0[jj * 4 + 3] * rl0);
        float4 w1 = make_float4(o1[jj * 4 + 0] * rl1, o1[jj * 4 + 1] * rl1,
                                o1[jj * 4 + 2] * rl1, o1[jj * 4 + 3] * rl1);
        *(float4*)&o[base0 + jj * 32 + tx * 4] = w0;
        *(float4*)&o[base1 + jj * 32 + tx * 4] = w1;
    }
}

// ---------------------------------------------------------------------------
extern "C" void kernel_launch(void* const* d_in, const int* in_sizes, int n_in,
                              void* d_out, int out_size)
{
    const float* x   = (const float*)d_in[0];
    const float* Wq  = (const float*)d_in[1];
    const float* bq  = (const float*)d_in[2];
    const float* Wk  = (const float*)d_in[3];
    const float* bk  = (const float*)d_in[4];
    const float* Wv  = (const float*)d_in[5];
    const float* bv  = (const float*)d_in[6];
    const float* Wo  = (const float*)d_in[7];
    const float* bo  = (const float*)d_in[8];
    const float* qns = (const float*)d_in[9];
    const float* kns = (const float*)d_in[10];
    float* out = (float*)d_out;

    float *q_buf, *k_buf, *v_buf, *ao_buf;
    cudaGetSymbolAddress((void**)&q_buf,  g_q);
    cudaGetSymbolAddress((void**)&k_buf,  g_k);
    cudaGetSymbolAddress((void**)&v_buf,  g_v);
    cudaGetSymbolAddress((void**)&ao_buf, g_ao);

    __half *xhi, *xlo, *aohi, *aolo, *wqh, *wql, *woh, *wol, *wkh, *wkl, *wvh, *wvl;
    cudaGetSymbolAddress((void**)&xhi,  g_xhi);
    cudaGetSymbolAddress((void**)&xlo,  g_xlo);
    cudaGetSymbolAddress((void**)&aohi, g_aohi);
    cudaGetSymbolAddress((void**)&aolo, g_aolo);
    cudaGetSymbolAddress((void**)&wqh,  g_wqh);
    cudaGetSymbolAddress((void**)&wql,  g_wql);
    cudaGetSymbolAddress((void**)&woh,  g_woh);
    cudaGetSymbolAddress((void**)&wol,  g_wol);
    cudaGetSymbolAddress((void**)&wkh,  g_wkh);
    cudaGetSymbolAddress((void**)&wkl,  g_wkl);
    cudaGetSymbolAddress((void**)&wvh,  g_wvh);
    cudaGetSymbolAddress((void**)&wvl,  g_wvl);

    cudaFuncSetAttribute(gemm_hmma, cudaFuncAttributeMaxDynamicSharedMemorySize, GEMM_SMEM);

    const int n4 = MROWS * DIM / 4;

    // conversions
    convert_split<<<(n4 + 255) / 256, 256>>>(x, xhi, xlo, n4);
    transpose_split<<<dim3(DIM / 32, DIM / 32), dim3(32, 8)>>>(Wq, wqh, wql, DIM, DIM);
    transpose_split<<<dim3(KVD / 32, DIM / 32), dim3(32, 8)>>>(Wk, wkh, wkl, DIM, KVD);
    transpose_split<<<dim3(KVD / 32, DIM / 32), dim3(32, 8)>>>(Wv, wvh, wvl, DIM, KVD);
    transpose_split<<<dim3(DIM / 32, DIM / 32), dim3(32, 8)>>>(Wo, woh, wol, DIM, DIM);

    // projections (HMMA)
    gemm_hmma<<<dim3(DIM / BN, MROWS / BM), 256, GEMM_SMEM>>>(
        xhi, xlo, wqh, wql, bq, q_buf, DIM);
    gemm_hmma<<<dim3(KVD / BN, MROWS / BM), 256, GEMM_SMEM>>>(
        xhi, xlo, wkh, wkl, bk, k_buf, KVD);
    gemm_hmma<<<dim3(KVD / BN, MROWS / BM), 256, GEMM_SMEM>>>(
        xhi, xlo, wvh, wvl, bv, v_buf, KVD);

    // rmsnorm + rope (q carries full 1/hd logit scaling)
    norm_rope<<<dim3(MROWS, NH), 64>>>(q_buf, qns, NH, 1.0f / (float)HD);
    norm_rope<<<dim3(MROWS, NG), 64>>>(k_buf, kns, NG, 1.0f);

    // attention
    flash_attn<<<dim3(SEQ / 32, NH, BATCH), 128>>>(q_buf, k_buf, v_buf, ao_buf);

    // output projection
    convert_split<<<(n4 + 255) / 256, 256>>>(ao_buf, aohi, aolo, n4);
    gemm_hmma<<<dim3(DIM / BN, MROWS / BM), 256, GEMM_SMEM>>>(
        aohi, aolo, woh, wol, bo, out, DIM);
}

// round 4
// speedup vs baseline: 3.3511x; 1.5490x over previous
#include <cuda_runtime.h>
#include <cuda_fp16.h>
#include <cstdint>
#include <math.h>

#define BATCH 16
#define SEQ   512
#define DIM   2048
#define NH    16
#define NG    4
#define HD    128
#define MROWS (BATCH*SEQ)   // 8192
#define KVD   (NG*HD)       // 512

// ---------------------------------------------------------------------------
// scratch (device globals — no allocation allowed)
// ---------------------------------------------------------------------------
__device__ float g_q[(size_t)MROWS * DIM];      // q proj fp32 (b,s,H,hd)
__device__ float g_k[(size_t)MROWS * KVD];      // k proj fp32 (b,s,G,hd)
__device__ float g_v[(size_t)MROWS * KVD];      // v proj fp32 (b,s,G,hd)

__device__ __half g_xhi[(size_t)MROWS * DIM];
__device__ __half g_xlo[(size_t)MROWS * DIM];
__device__ __half g_aoh[(size_t)MROWS * DIM];   // attn out hi (b,s,H,hd)
__device__ __half g_aol[(size_t)MROWS * DIM];
__device__ __half g_wqh[(size_t)DIM * DIM];
__device__ __half g_wql[(size_t)DIM * DIM];
__device__ __half g_woh[(size_t)DIM * DIM];
__device__ __half g_wol[(size_t)DIM * DIM];
__device__ __half g_wkh[(size_t)KVD * DIM];
__device__ __half g_wkl[(size_t)KVD * DIM];
__device__ __half g_wvh[(size_t)KVD * DIM];
__device__ __half g_wvl[(size_t)KVD * DIM];

// attention operand buffers, (b, head, s, hd) layout, fp16 hi/lo
__device__ __half g_qah[(size_t)MROWS * DIM];
__device__ __half g_qal[(size_t)MROWS * DIM];
__device__ __half g_kah[(size_t)MROWS * KVD];
__device__ __half g_kal[(size_t)MROWS * KVD];
__device__ __half g_vah[(size_t)MROWS * KVD];
__device__ __half g_val[(size_t)MROWS * KVD];

// ---------------------------------------------------------------------------
// helpers
// ---------------------------------------------------------------------------
__device__ __forceinline__ uint32_t smem_to_u32(const void* p) {
    uint32_t a;
    asm("{ .reg .u64 t; cvta.to.shared.u64 t, %1; cvt.u32.u64 %0, t; }" : "=r"(a) : "l"(p));
    return a;
}
#define SMEM_SWIZZLE_128B(bo) ((bo) ^ (((bo) >> 3) & 0x70))

__device__ __forceinline__ void cp16(uint32_t s, const void* g) {
    asm volatile("cp.async.cg.shared.global [%0], [%1], 16;" :: "r"(s), "l"(g) : "memory");
}
#define CP_COMMIT() asm volatile("cp.async.commit_group;" ::: "memory")
__device__ __forceinline__ void ldm4(uint32_t* r, uint32_t a) {
    asm volatile("ldmatrix.sync.aligned.m8n8.x4.shared.b16 {%0,%1,%2,%3}, [%4];"
                 : "=r"(r[0]), "=r"(r[1]), "=r"(r[2]), "=r"(r[3]) : "r"(a));
}
__device__ __forceinline__ void ldm4t(uint32_t* r, uint32_t a) {
    asm volatile("ldmatrix.sync.aligned.m8n8.x4.trans.shared.b16 {%0,%1,%2,%3}, [%4];"
                 : "=r"(r[0]), "=r"(r[1]), "=r"(r[2]), "=r"(r[3]) : "r"(a));
}
__device__ __forceinline__ void mma16816(float* d, const uint32_t* a, const uint32_t* b) {
    asm volatile(
        "mma.sync.aligned.m16n8k16.row.col.f32.f16.f16.f32 "
        "{%0,%1,%2,%3},{%4,%5,%6,%7},{%8,%9},{%0,%1,%2,%3};"
        : "+f"(d[0]), "+f"(d[1]), "+f"(d[2]), "+f"(d[3])
        : "r"(a[0]), "r"(a[1]), "r"(a[2]), "r"(a[3]), "r"(b[0]), "r"(b[1]));
}
__device__ __forceinline__ uint32_t pk2h(float a, float b) {
    __half2 h = __floats2half2_rn(a, b);
    return *reinterpret_cast<uint32_t*>(&h);
}

// ---------------------------------------------------------------------------
// convert fp32 -> fp16 hi + fp16 lo (residual)
// ---------------------------------------------------------------------------
__global__ __launch_bounds__(256) void convert_split(
    const float* __restrict__ in, __half* __restrict__ hi,
    __half* __restrict__ lo, int n4)
{
    int i = blockIdx.x * 256 + threadIdx.x;
    if (i >= n4) return;
    float4 v = ((const float4*)in)[i];
    float hx = __half2float(__float2half_rn(v.x));
    float hy = __half2float(__float2half_rn(v.y));
    float hz = __half2float(__float2half_rn(v.z));
    float hw = __half2float(__float2half_rn(v.w));
    uint2 ph, pl;
    ph.x = pk2h(v.x, v.y); ph.y = pk2h(v.z, v.w);
    pl.x = pk2h(v.x - hx, v.y - hy); pl.y = pk2h(v.z - hz, v.w - hw);
    ((uint2*)hi)[i] = ph;
    ((uint2*)lo)[i] = pl;
}

// ---------------------------------------------------------------------------
// W [K, N] fp32 -> W^T [N, K] fp16 hi/lo
// ---------------------------------------------------------------------------
__global__ __launch_bounds__(256) void transpose_split(
    const float* __restrict__ W, __half* __restrict__ Th,
    __half* __restrict__ Tl, int K, int N)
{
    __shared__ float tile[32][33];
    int n0 = blockIdx.x * 32, k0 = blockIdx.y * 32;
    int tx = threadIdx.x, ty = threadIdx.y;   // 32 x 8
    #pragma unroll
    for (int j = ty; j < 32; j += 8)
        tile[j][tx] = W[(size_t)(k0 + j) * N + n0 + tx];
    __syncthreads();
    #pragma unroll
    for (int j = ty; j < 32; j += 8) {
        float v = tile[tx][j];
        __half h = __float2half_rn(v);
        float r = v - __half2float(h);
        size_t o = (size_t)(n0 + j) * K + k0 + tx;
        Th[o] = h;
        Tl[o] = __float2half_rn(r);
    }
}

// ---------------------------------------------------------------------------
// HMMA split-3 fp16 GEMM (as round 3, unchanged — it passed)
// ---------------------------------------------------------------------------
#define BM 128
#define BN 128
#define BK 64
#define NCH (DIM / BK)   // 32
#define STG_BYTES 65536
#define OFF_AH 0
#define OFF_AL 16384
#define OFF_BH 32768
#define OFF_BL 49152
#define GEMM_SMEM (2 * STG_BYTES)   // 131072

__global__ __launch_bounds__(256, 1) void gemm_hmma(
    const __half* __restrict__ Ahg, const __half* __restrict__ Alg,
    const __half* __restrict__ Bhg, const __half* __restrict__ Blg,
    const float* __restrict__ bias, float* __restrict__ C, int N)
{
    extern __shared__ char sm[];
    uint32_t sb = smem_to_u32(sm);
    int tid = threadIdx.x, lane = tid & 31, wid = tid >> 5;
    int wm = wid & 1, wn = wid >> 1;
    int bx = blockIdx.x * BN, by = blockIdx.y * BM;

    auto load_stage = [&](int s, int kt) {
        int k0 = kt * BK;
        uint32_t base = sb + s * STG_BYTES;
        #pragma unroll
        for (int t = 0; t < 4; t++) {
            int idx = tid + t * 256;
            int r = idx >> 3, c16 = idx & 7;
            uint32_t swz = SMEM_SWIZZLE_128B((uint32_t)(r * 128 + c16 * 16));
            size_t ga = (size_t)(by + r) * DIM + k0 + c16 * 8;
            size_t gb = (size_t)(bx + r) * DIM + k0 + c16 * 8;
            cp16(base + OFF_AH + swz, Ahg + ga);
            cp16(base + OFF_AL + swz, Alg + ga);
            cp16(base + OFF_BH + swz, Bhg + gb);
            cp16(base + OFF_BL + swz, Blg + gb);
        }
    };

    float d[4][4][4];
    #pragma unroll
    for (int i = 0; i < 4; i++)
        #pragma unroll
        for (int j = 0; j < 4; j++)
            #pragma unroll
            for (int q = 0; q < 4; q++) d[i][j][q] = 0.f;

    load_stage(0, 0);
    CP_COMMIT();
    load_stage(1, 1);
    CP_COMMIT();

    for (int kt = 0; kt < NCH; kt++) {
        if (kt < NCH - 1) asm volatile("cp.async.wait_group 1;" ::: "memory");
        else              asm volatile("cp.async.wait_group 0;" ::: "memory");
        __syncthreads();

        int s = kt & 1;
        uint32_t base = sb + s * STG_BYTES;
        int arow = wm * 64 + (lane & 15);
        int bro  = wn * 32 + (lane & 7) + ((lane >> 4) << 3);
        int bkh  = ((lane >> 3) & 1) << 3;

        #pragma unroll
        for (int ks = 0; ks < 4; ks++) {
            int acol = ks * 16 + ((lane >> 4) << 3);
            uint32_t ah[4][4], al[4][4], bh[4][2], bl[4][2];
            #pragma unroll
            for (int mf = 0; mf < 4; mf++) {
                uint32_t off = SMEM_SWIZZLE_128B(
                    (uint32_t)((arow + mf * 16) * 128 + acol * 2));
                ldm4(ah[mf], base + OFF_AH + off);
                ldm4(al[mf], base + OFF_AL + off);
            }
            #pragma unroll
            for (int j2 = 0; j2 < 2; j2++) {
                uint32_t off = SMEM_SWIZZLE_128B(
                    (uint32_t)((bro + j2 * 16) * 128 + (ks * 16 + bkh) * 2));
                uint32_t r[4];
                ldm4(r, base + OFF_BH + off);
                bh[j2 * 2][0] = r[0]; bh[j2 * 2][1] = r[1];
                bh[j2 * 2 + 1][0] = r[2]; bh[j2 * 2 + 1][1] = r[3];
                ldm4(r, base + OFF_BL + off);
                bl[j2 * 2][0] = r[0]; bl[j2 * 2][1] = r[1];
                bl[j2 * 2 + 1][0] = r[2]; bl[j2 * 2 + 1][1] = r[3];
            }
            #pragma unroll
            for (int mf = 0; mf < 4; mf++)
                #pragma unroll
                for (int nf = 0; nf < 4; nf++) {
                    mma16816(d[mf][nf], ah[mf], bh[nf]);
                    mma16816(d[mf][nf], ah[mf], bl[nf]);
                    mma16816(d[mf][nf], al[mf], bh[nf]);
                }
        }
        __syncthreads();

        if (kt + 2 < NCH) {
            load_stage(s, kt + 2);
            CP_COMMIT();
        }
    }

    int row0 = by + wm * 64 + (lane >> 2);
    int col0 = bx + wn * 32 + (lane & 3) * 2;
    #pragma unroll
    for (int mf = 0; mf < 4; mf++)
        #pragma unroll
        for (int nf = 0; nf < 4; nf++) {
            int r = row0 + mf * 16;
            int c = col0 + nf * 8;
            float b0 = bias[c], b1 = bias[c + 1];
            float2 v0 = make_float2(d[mf][nf][0] + b0, d[mf][nf][1] + b1);
            float2 v1 = make_float2(d[mf][nf][2] + b0, d[mf][nf][3] + b1);
            *(float2*)&C[(size_t)r * N + c] = v0;
            *(float2*)&C[(size_t)(r + 8) * N + c] = v1;
        }
}

// ---------------------------------------------------------------------------
// RMSNorm + RoPE; reads fp32 (b,s,nh,hd), writes fp16 hi/lo (b,head,s,hd)
// ---------------------------------------------------------------------------
__global__ __launch_bounds__(64) void norm_rope_split(
    const float* __restrict__ in, __half2* __restrict__ oh,
    __half2* __restrict__ ol, const float* __restrict__ scale,
    int nheads, float extra_scale)
{
    int row = blockIdx.x;          // b*SEQ + s
    int h   = blockIdx.y;
    int pos = row & (SEQ - 1);
    int b   = row >> 9;            // SEQ = 512
    const float* p = in + ((size_t)row * nheads + h) * HD;

    int i = threadIdx.x;
    float2 xv = *(const float2*)&p[2 * i];

    float ss = xv.x * xv.x + xv.y * xv.y;
    #pragma unroll
    for (int off = 16; off; off >>= 1)
        ss += __shfl_xor_sync(0xffffffffu, ss, off);
    __shared__ float sw[2];
    if ((threadIdx.x & 31) == 0) sw[threadIdx.x >> 5] = ss;
    __syncthreads();
    float total = sw[0] + sw[1];
    float rinv = rsqrtf(total * (1.0f / HD) + 1e-6f);

    float x1 = xv.x * rinv * scale[2 * i];
    float x2 = xv.y * rinv * scale[2 * i + 1];

    float inv_freq = expf(-(float)i * (9.210340371976184f / 64.0f));
    float fr = (float)pos * inv_freq;
    float sn = sinf(fr), cs = cosf(fr);

    float o1 = (x1 * cs - x2 * sn) * extra_scale;
    float o2 = (x1 * sn + x2 * cs) * extra_scale;

    __half h1 = __float2half_rn(o1), h2 = __float2half_rn(o2);
    float r1 = o1 - __half2float(h1), r2 = o2 - __half2float(h2);

    size_t ob = (((size_t)(b * nheads + h) * SEQ + pos) * HD) / 2 + i;
    oh[ob] = __halves2half2(h1, h2);
    ol[ob] = __halves2half2(__float2half_rn(r1), __float2half_rn(r2));
}

// ---------------------------------------------------------------------------
// V: fp32 (b,s,G,hd) -> fp16 hi/lo (b,g,s,hd)
// ---------------------------------------------------------------------------
__global__ __launch_bounds__(128) void v_split(
    const float* __restrict__ v, __half2* __restrict__ vh, __half2* __restrict__ vl)
{
    int idx = blockIdx.x * 128 + threadIdx.x;   // over MROWS*KVD/2
    int hd2 = idx & 63;
    int r = idx >> 6;          // (b*SEQ+s)*NG + g
    int g = r & (NG - 1);
    int t = r >> 2;            // b*SEQ + s
    int s = t & (SEQ - 1);
    int b = t >> 9;
    float2 x = ((const float2*)v)[idx];
    __half h1 = __float2half_rn(x.x), h2 = __float2half_rn(x.y);
    float r1 = x.x - __half2float(h1), r2 = x.y - __half2float(h2);
    size_t o = (((size_t)(b * NG + g) * SEQ + s) * HD) / 2 + hd2;
    vh[o] = __halves2half2(h1, h2);
    vl[o] = __halves2half2(__float2half_rn(r1), __float2half_rn(r2));
}

// ---------------------------------------------------------------------------
// HMMA flash attention. BR=128, BC=64, 8 warps. Split-3 fp16 throughout.
// q carries full 1/hd scaling. Causal. Writes O as fp16 hi/lo (b,s,H,hd).
// smem: Q hi/lo 64KB resident + 2-stage K/V hi/lo (64KB each) = 192KB
// ---------------------------------------------------------------------------
#define FA_SMEM (196608)

__global__ __launch_bounds__(256, 1) void flash_attn_hmma(
    const __half* __restrict__ qh, const __half* __restrict__ ql,
    const __half* __restrict__ kh, const __half* __restrict__ kl,
    const __half* __restrict__ vh, const __half* __restrict__ vl,
    __half* __restrict__ aoh, __half* __restrict__ aol)
{
    extern __shared__ char sm[];
    uint32_t sb = smem_to_u32(sm);
    int qb = (gridDim.x - 1) - blockIdx.x;   // heavy tiles first
    int h = blockIdx.y, b = blockIdx.z;
    int g = h >> 2;
    int tid = threadIdx.x, lane = tid & 31, wid = tid >> 5;

    const size_t qbase  = ((size_t)(b * NH + h) * SEQ + qb * 128) * HD;
    const size_t kvbase = ((size_t)(b * NG + g) * SEQ) * HD;

    const uint32_t QH = sb, QL = sb + 32768;
    // stage s base: sb + 65536 + s*65536; offsets KH 0, KL 16384, VH 32768, VL 49152

    auto load_q = [&]() {
        #pragma unroll
        for (int t = 0; t < 8; t++) {
            int idx = tid + t * 256;
            int r = idx >> 4, c16 = idx & 15;
            uint32_t off = (uint32_t)((c16 >> 3) * 16384) +
                           SMEM_SWIZZLE_128B((uint32_t)(r * 128 + (c16 & 7) * 16));
            size_t go = qbase + (size_t)r * HD + c16 * 8;
            cp16(QH + off, qh + go);
            cp16(QL + off, ql + go);
        }
    };
    auto load_kv = [&](int s, int kt) {
        uint32_t base = sb + 65536 + s * 65536;
        size_t kb = kvbase + (size_t)kt * 64 * HD;
        #pragma unroll
        for (int t = 0; t < 4; t++) {
            int idx = tid + t * 256;
            int r = idx >> 4, c16 = idx & 15;
            uint32_t off = (uint32_t)((c16 >> 3) * 8192) +
                           SMEM_SWIZZLE_128B((uint32_t)(r * 128 + (c16 & 7) * 16));
            size_t go = kb + (size_t)r * HD + c16 * 8;
            cp16(base + off,         kh + go);
            cp16(base + 16384 + off, kl + go);
            cp16(base + 32768 + off, vh + go);
            cp16(base + 49152 + off, vl + go);
        }
    };

    int nkt = 2 * qb + 2;
    load_q();
    load_kv(0, 0);
    CP_COMMIT();
    load_kv(1, 1);
    CP_COMMIT();

    float o[16][4];
    #pragma unroll
    for (int i = 0; i < 16; i++)
        #pragma unroll
        for (int j = 0; j < 4; j++) o[i][j] = 0.f;
    float mA = -1e30f, mB = -1e30f, lA = 0.f, lB = 0.f;

    int row0 = wid * 16;
    int sq = qb * 128 + row0;      // warp's min q row (global)

    for (int kt = 0; kt < nkt; kt++) {
        if (kt < nkt - 1) asm volatile("cp.async.wait_group 1;" ::: "memory");
        else              asm volatile("cp.async.wait_group 0;" ::: "memory");
        __syncthreads();

        int st = kt & 1;
        uint32_t KHb = sb + 65536 + st * 65536;
        uint32_t KLb = KHb + 16384, VHb = KHb + 32768, VLb = KHb + 49152;

        bool active = (kt * 64 <= sq + 15);
        if (active) {
            float sc[8][4];
            #pragma unroll
            for (int i = 0; i < 8; i++)
                #pragma unroll
                for (int j = 0; j < 4; j++) sc[i][j] = 0.f;

            int aro  = row0 + (lane & 15);
            int kro  = (lane & 7) + ((lane >> 4) << 3);
            int bkh  = ((lane >> 3) & 1) << 3;

            // S = Q K^T
            #pragma unroll
            for (int ks = 0; ks < 8; ks++) {
                int chk  = ks >> 2;
                int acol = (ks & 3) * 16 + ((lane >> 4) << 3);
                uint32_t aoff = (uint32_t)(chk * 16384) +
                                SMEM_SWIZZLE_128B((uint32_t)(aro * 128 + acol * 2));
                uint32_t ah[4], al[4];
                ldm4(ah, QH + aoff);
                ldm4(al, QL + aoff);

                int bcol = (ks & 3) * 16 + bkh;
                uint32_t bh[8][2], bl[8][2];
                #pragma unroll
                for (int j2 = 0; j2 < 4; j2++) {
                    uint32_t boff = (uint32_t)(chk * 8192) +
                        SMEM_SWIZZLE_128B((uint32_t)((j2 * 16 + kro) * 128 + bcol * 2));
                    uint32_t r[4];
                    ldm4(r, KHb + boff);
                    bh[2*j2][0] = r[0]; bh[2*j2][1] = r[1];
                    bh[2*j2+1][0] = r[2]; bh[2*j2+1][1] = r[3];
                    ldm4(r, KLb + boff);
                    bl[2*j2][0] = r[0]; bl[2*j2][1] = r[1];
                    bl[2*j2+1][0] = r[2]; bl[2*j2+1][1] = r[3];
                }
                #pragma unroll
                for (int nf = 0; nf < 8; nf++) {
                    mma16816(sc[nf], ah, bh[nf]);
                    mma16816(sc[nf], ah, bl[nf]);
                    mma16816(sc[nf], al, bh[nf]);
                }
            }

            // causal mask (boundary tiles only)
            if (kt * 64 + 63 > sq) {
                int rA = sq + (lane >> 2), rB = rA + 8;
                #pragma unroll
                for (int nf = 0; nf < 8; nf++) {
                    int c0 = kt * 64 + nf * 8 + 2 * (lane & 3);
                    if (c0     > rA) sc[nf][0] = -1e30f;
                    if (c0 + 1 > rA) sc[nf][1] = -1e30f;
                    if (c0     > rB) sc[nf][2] = -1e30f;
                    if (c0 + 1 > rB) sc[nf][3] = -1e30f;
                }
            }

            // online softmax (rows rA = lane/4, rB = rA+8; quad-local)
            float mtA = -1e30f, mtB = -1e30f;
            #pragma unroll
            for (int nf = 0; nf < 8; nf++) {
                mtA = fmaxf(mtA, fmaxf(sc[nf][0], sc[nf][1]));
                mtB = fmaxf(mtB, fmaxf(sc[nf][2], sc[nf][3]));
            }
            mtA = fmaxf(mtA, __shfl_xor_sync(0xffffffffu, mtA, 1));
            mtA = fmaxf(mtA, __shfl_xor_sync(0xffffffffu, mtA, 2));
            mtB = fmaxf(mtB, __shfl_xor_sync(0xffffffffu, mtB, 1));
            mtB = fmaxf(mtB, __shfl_xor_sync(0xffffffffu, mtB, 2));
            float nmA = fmaxf(mA, mtA), nmB = fmaxf(mB, mtB);
            float alA = __expf(mA - nmA), alB = __expf(mB - nmB);

            float suA = 0.f, suB = 0.f;
            #pragma unroll
            for (int nf = 0; nf < 8; nf++) {
                sc[nf][0] = __expf(sc[nf][0] - nmA); suA += sc[nf][0];
                sc[nf][1] = __expf(sc[nf][1] - nmA); suA += sc[nf][1];
                sc[nf][2] = __expf(sc[nf][2] - nmB); suB += sc[nf][2];
                sc[nf][3] = __expf(sc[nf][3] - nmB); suB += sc[nf][3];
            }
            suA += __shfl_xor_sync(0xffffffffu, suA, 1);
            suA += __shfl_xor_sync(0xffffffffu, suA, 2);
            suB += __shfl_xor_sync(0xffffffffu, suB, 1);
            suB += __shfl_xor_sync(0xffffffffu, suB, 2);
            lA = lA * alA + suA;
            lB = lB * alB + suB;
            mA = nmA; mB = nmB;
            #pragma unroll
            for (int nf = 0; nf < 16; nf++) {
                o[nf][0] *= alA; o[nf][1] *= alA;
                o[nf][2] *= alB; o[nf][3] *= alB;
            }

            // O += P V
            int vro = (lane & 7) + (((lane >> 3) & 1) << 3);
            int vch = (lane >> 4) << 3;
            #pragma unroll
            for (int kf = 0; kf < 4; kf++) {
                // P fragments (register-direct from C layout)
                uint32_t aPh[4], aPl[4];
                {
                    float p0 = sc[2*kf][0],   p1 = sc[2*kf][1];
                    float p2 = sc[2*kf][2],   p3 = sc[2*kf][3];
                    float p4 = sc[2*kf+1][0], p5 = sc[2*kf+1][1];
                    float p6 = sc[2*kf+1][2], p7 = sc[2*kf+1][3];
                    __half h0 = __float2half_rn(p0), h1 = __float2half_rn(p1);
                    __half h2 = __float2half_rn(p2), h3 = __float2half_rn(p3);
                    __half h4 = __float2half_rn(p4), h5 = __float2half_rn(p5);
                    __half h6 = __float2half_rn(p6), h7 = __float2half_rn(p7);
                    aPh[0] = pk2h(p0, p1); aPh[1] = pk2h(p2, p3);
                    aPh[2] = pk2h(p4, p5); aPh[3] = pk2h(p6, p7);
                    aPl[0] = pk2h(p0 - __half2float(h0), p1 - __half2float(h1));
                    aPl[1] = pk2h(p2 - __half2float(h2), p3 - __half2float(h3));
                    aPl[2] = pk2h(p4 - __half2float(h4), p5 - __half2float(h5));
                    aPl[3] = pk2h(p6 - __half2float(h6), p7 - __half2float(h7));
                }
                #pragma unroll
                for (int j2 = 0; j2 < 8; j2++) {
                    int chk  = j2 >> 2;
                    int wcol = (j2 & 3) * 16 + vch;
                    uint32_t voff = (uint32_t)(chk * 8192) +
                        SMEM_SWIZZLE_128B((uint32_t)((kf * 16 + vro) * 128 + wcol * 2));
                    uint32_t rh[4], rl[4];
                    ldm4t(rh, VHb + voff);
                    ldm4t(rl, VLb + voff);
                    uint32_t bh0[2] = {rh[0], rh[1]}, bh1[2] = {rh[2], rh[3]};
                    uint32_t bl0[2] = {rl[0], rl[1]}, bl1[2] = {rl[2], rl[3]};
                    mma16816(o[2*j2],   aPh, bh0);
                    mma16816(o[2*j2],   aPh, bl0);
                    mma16816(o[2*j2],   aPl, bh0);
                    mma16816(o[2*j2+1], aPh, bh1);
                    mma16816(o[2*j2+1], aPh, bl1);
                    mma16816(o[2*j2+1], aPl, bh1);
                }
            }
        }
        __syncthreads();

        if (kt + 2 < nkt) {
            load_kv(st, kt + 2);
            CP_COMMIT();
        }
    }

    // epilogue: O/l -> fp16 hi/lo at (b,s,H,hd)
    float rlA = 1.0f / lA, rlB = 1.0f / lB;
    int sA = sq + (lane >> 2), sB = sA + 8;
    size_t oA = ((size_t)(b * SEQ + sA) * NH + h) * HD;
    size_t oB = ((size_t)(b * SEQ + sB) * NH + h) * HD;
    #pragma unroll
    for (int nf = 0; nf < 16; nf++) {
        int hd = nf * 8 + 2 * (lane & 3);
        float e0 = o[nf][0] * rlA, e1 = o[nf][1] * rlA;
        float e2 = o[nf][2] * rlB, e3 = o[nf][3] * rlB;
        __half h0 = __float2half_rn(e0), h1 = __float2half_rn(e1);
        __half h2 = __float2half_rn(e2), h3 = __float2half_rn(e3);
        *(__half2*)&aoh[oA + hd] = __halves2half2(h0, h1);
        *(__half2*)&aol[oA + hd] = __halves2half2(
            __float2half_rn(e0 - __half2float(h0)), __float2half_rn(e1 - __half2float(h1)));
        *(__half2*)&aoh[oB + hd] = __halves2half2(h2, h3);
        *(__half2*)&aol[oB + hd] = __halves2half2(
            __float2half_rn(e2 - __half2float(h2)), __float2half_rn(e3 - __half2float(h3)));
    }
}

// ---------------------------------------------------------------------------
extern "C" void kernel_launch(void* const* d_in, const int* in_sizes, int n_in,
                              void* d_out, int out_size)
{
    const float* x   = (const float*)d_in[0];
    const float* Wq  = (const float*)d_in[1];
    const float* bq  = (const float*)d_in[2];
    const float* Wk  = (const float*)d_in[3];
    const float* bk  = (const float*)d_in[4];
    const float* Wv  = (const float*)d_in[5];
    const float* bv  = (const float*)d_in[6];
    const float* Wo  = (const float*)d_in[7];
    const float* bo  = (const float*)d_in[8];
    const float* qns = (const float*)d_in[9];
    const float* kns = (const float*)d_in[10];
    float* out = (float*)d_out;

    float *q_buf, *k_buf, *v_buf;
    cudaGetSymbolAddress((void**)&q_buf, g_q);
    cudaGetSymbolAddress((void**)&k_buf, g_k);
    cudaGetSymbolAddress((void**)&v_buf, g_v);

    __half *xhi, *xlo, *aoh, *aol, *wqh, *wql, *woh, *wol, *wkh, *wkl, *wvh, *wvl;
    __half *qah, *qal, *kah, *kal, *vah, *val;
    cudaGetSymbolAddress((void**)&xhi, g_xhi);
    cudaGetSymbolAddress((void**)&xlo, g_xlo);
    cudaGetSymbolAddress((void**)&aoh, g_aoh);
    cudaGetSymbolAddress((void**)&aol, g_aol);
    cudaGetSymbolAddress((void**)&wqh, g_wqh);
    cudaGetSymbolAddress((void**)&wql, g_wql);
    cudaGetSymbolAddress((void**)&woh, g_woh);
    cudaGetSymbolAddress((void**)&wol, g_wol);
    cudaGetSymbolAddress((void**)&wkh, g_wkh);
    cudaGetSymbolAddress((void**)&wkl, g_wkl);
    cudaGetSymbolAddress((void**)&wvh, g_wvh);
    cudaGetSymbolAddress((void**)&wvl, g_wvl);
    cudaGetSymbolAddress((void**)&qah, g_qah);
    cudaGetSymbolAddress((void**)&qal, g_qal);
    cudaGetSymbolAddress((void**)&kah, g_kah);
    cudaGetSymbolAddress((void**)&kal, g_kal);
    cudaGetSymbolAddress((void**)&vah, g_vah);
    cudaGetSymbolAddress((void**)&val, g_val);

    cudaFuncSetAttribute(gemm_hmma, cudaFuncAttributeMaxDynamicSharedMemorySize, GEMM_SMEM);
    cudaFuncSetAttribute(flash_attn_hmma, cudaFuncAttributeMaxDynamicSharedMemorySize, FA_SMEM);

    const int n4 = MROWS * DIM / 4;

    // conversions
    convert_split<<<(n4 + 255) / 256, 256>>>(x, xhi, xlo, n4);
    transpose_split<<<dim3(DIM / 32, DIM / 32), dim3(32, 8)>>>(Wq, wqh, wql, DIM, DIM);
    transpose_split<<<dim3(KVD / 32, DIM / 32), dim3(32, 8)>>>(Wk, wkh, wkl, DIM, KVD);
    transpose_split<<<dim3(KVD / 32, DIM / 32), dim3(32, 8)>>>(Wv, wvh, wvl, DIM, KVD);
    transpose_split<<<dim3(DIM / 32, DIM / 32), dim3(32, 8)>>>(Wo, woh, wol, DIM, DIM);

    // projections (HMMA)
    gemm_hmma<<<dim3(DIM / BN, MROWS / BM), 256, GEMM_SMEM>>>(
        xhi, xlo, wqh, wql, bq, q_buf, DIM);
    gemm_hmma<<<dim3(KVD / BN, MROWS / BM), 256, GEMM_SMEM>>>(
        xhi, xlo, wkh, wkl, bk, k_buf, KVD);
    gemm_hmma<<<dim3(KVD / BN, MROWS / BM), 256, GEMM_SMEM>>>(
        xhi, xlo, wvh, wvl, bv, v_buf, KVD);

    // rmsnorm + rope -> fp16 hi/lo in (b,head,s,hd); q carries full 1/hd
    norm_rope_split<<<dim3(MROWS, NH), 64>>>(q_buf, (__half2*)qah, (__half2*)qal,
                                             qns, NH, 1.0f / (float)HD);
    norm_rope_split<<<dim3(MROWS, NG), 64>>>(k_buf, (__half2*)kah, (__half2*)kal,
                                             kns, NG, 1.0f);
    v_split<<<(MROWS * KVD / 2) / 128, 128>>>(v_buf, (__half2*)vah, (__half2*)val);

    // attention (HMMA)
    flash_attn_hmma<<<dim3(SEQ / 128, NH, BATCH), 256, FA_SMEM>>>(
        qah, qal, kah, kal, vah, val, aoh, aol);

    // output projection
    gemm_hmma<<<dim3(DIM / BN, MROWS / BM), 256, GEMM_SMEM>>>(
        aoh, aol, woh, wol, bo, out, DIM);
}

// round 5
// speedup vs baseline: 3.5108x; 1.0476x over previous
#include <cuda_runtime.h>
#include <cuda_fp16.h>
#include <cstdint>
#include <math.h>

#define BATCH 16
#define SEQ   512
#define DIM   2048
#define NH    16
#define NG    4
#define HD    128
#define MROWS (BATCH*SEQ)   // 8192
#define KVD   (NG*HD)       // 512
#define NQKV  (DIM + 2*KVD) // 3072

// ---------------------------------------------------------------------------
// scratch (device globals — no allocation allowed)
// ---------------------------------------------------------------------------
__device__ __half g_xhi[(size_t)MROWS * DIM];
__device__ __half g_xlo[(size_t)MROWS * DIM];
__device__ __half g_aoh[(size_t)MROWS * DIM];   // attn out hi (b,s,H,hd)
__device__ __half g_aol[(size_t)MROWS * DIM];
__device__ __half g_wh[(size_t)NQKV * DIM];     // [Wq^T; Wk^T; Wv^T] fp16 hi
__device__ __half g_wl[(size_t)NQKV * DIM];
__device__ __half g_woh[(size_t)DIM * DIM];
__device__ __half g_wol[(size_t)DIM * DIM];
__device__ float  g_bqkv[NQKV];                 // [bq; bk; bv]

// attention operand buffers, (b, head, s, hd) layout, fp16 hi/lo
__device__ __half g_qah[(size_t)MROWS * DIM];
__device__ __half g_qal[(size_t)MROWS * DIM];
__device__ __half g_kah[(size_t)MROWS * KVD];
__device__ __half g_kal[(size_t)MROWS * KVD];
__device__ __half g_vah[(size_t)MROWS * KVD];
__device__ __half g_val[(size_t)MROWS * KVD];

// ---------------------------------------------------------------------------
// helpers
// ---------------------------------------------------------------------------
__device__ __forceinline__ uint32_t smem_to_u32(const void* p) {
    uint32_t a;
    asm("{ .reg .u64 t; cvta.to.shared.u64 t, %1; cvt.u32.u64 %0, t; }" : "=r"(a) : "l"(p));
    return a;
}
#define SMEM_SWIZZLE_128B(bo) ((bo) ^ (((bo) >> 3) & 0x70))

__device__ __forceinline__ void cp16(uint32_t s, const void* g) {
    asm volatile("cp.async.cg.shared.global [%0], [%1], 16;" :: "r"(s), "l"(g) : "memory");
}
#define CP_COMMIT() asm volatile("cp.async.commit_group;" ::: "memory")
__device__ __forceinline__ void ldm4(uint32_t* r, uint32_t a) {
    asm volatile("ldmatrix.sync.aligned.m8n8.x4.shared.b16 {%0,%1,%2,%3}, [%4];"
                 : "=r"(r[0]), "=r"(r[1]), "=r"(r[2]), "=r"(r[3]) : "r"(a));
}
__device__ __forceinline__ void ldm4t(uint32_t* r, uint32_t a) {
    asm volatile("ldmatrix.sync.aligned.m8n8.x4.trans.shared.b16 {%0,%1,%2,%3}, [%4];"
                 : "=r"(r[0]), "=r"(r[1]), "=r"(r[2]), "=r"(r[3]) : "r"(a));
}
__device__ __forceinline__ void mma16816(float* d, const uint32_t* a, const uint32_t* b) {
    asm volatile(
        "mma.sync.aligned.m16n8k16.row.col.f32.f16.f16.f32 "
        "{%0,%1,%2,%3},{%4,%5,%6,%7},{%8,%9},{%0,%1,%2,%3};"
        : "+f"(d[0]), "+f"(d[1]), "+f"(d[2]), "+f"(d[3])
        : "r"(a[0]), "r"(a[1]), "r"(a[2]), "r"(a[3]), "r"(b[0]), "r"(b[1]));
}
__device__ __forceinline__ uint32_t pk2h(float a, float b) {
    __half2 h = __floats2half2_rn(a, b);
    return *reinterpret_cast<uint32_t*>(&h);
}
// store float pair as hi/lo half2
__device__ __forceinline__ void split_store(__half* hp, __half* lp, size_t off,
                                            float a, float b) {
    __half ha = __float2half_rn(a), hb = __float2half_rn(b);
    *(__half2*)&hp[off] = __halves2half2(ha, hb);
    *(__half2*)&lp[off] = __halves2half2(
        __float2half_rn(a - __half2float(ha)), __float2half_rn(b - __half2float(hb)));
}

// ---------------------------------------------------------------------------
// convert fp32 -> fp16 hi + fp16 lo (residual)
// ---------------------------------------------------------------------------
__global__ __launch_bounds__(256) void convert_split(
    const float* __restrict__ in, __half* __restrict__ hi,
    __half* __restrict__ lo, int n4)
{
    int i = blockIdx.x * 256 + threadIdx.x;
    if (i >= n4) return;
    float4 v = ((const float4*)in)[i];
    float hx = __half2float(__float2half_rn(v.x));
    float hy = __half2float(__float2half_rn(v.y));
    float hz = __half2float(__float2half_rn(v.z));
    float hw = __half2float(__float2half_rn(v.w));
    uint2 ph, pl;
    ph.x = pk2h(v.x, v.y); ph.y = pk2h(v.z, v.w);
    pl.x = pk2h(v.x - hx, v.y - hy); pl.y = pk2h(v.z - hz, v.w - hw);
    ((uint2*)hi)[i] = ph;
    ((uint2*)lo)[i] = pl;
}

// ---------------------------------------------------------------------------
// W [K, N] fp32 -> W^T [N, K] fp16 hi/lo
// ---------------------------------------------------------------------------
__global__ __launch_bounds__(256) void transpose_split(
    const float* __restrict__ W, __half* __restrict__ Th,
    __half* __restrict__ Tl, int K, int N)
{
    __shared__ float tile[32][33];
    int n0 = blockIdx.x * 32, k0 = blockIdx.y * 32;
    int tx = threadIdx.x, ty = threadIdx.y;   // 32 x 8
    #pragma unroll
    for (int j = ty; j < 32; j += 8)
        tile[j][tx] = W[(size_t)(k0 + j) * N + n0 + tx];
    __syncthreads();
    #pragma unroll
    for (int j = ty; j < 32; j += 8) {
        float v = tile[tx][j];
        __half h = __float2half_rn(v);
        float r = v - __half2float(h);
        size_t o = (size_t)(n0 + j) * K + k0 + tx;
        Th[o] = h;
        Tl[o] = __float2half_rn(r);
    }
}

__global__ __launch_bounds__(256) void bias_concat(
    const float* __restrict__ bq, const float* __restrict__ bk,
    const float* __restrict__ bv, float* __restrict__ o)
{
    int i = blockIdx.x * 256 + threadIdx.x;
    if (i < DIM) o[i] = bq[i];
    else if (i < DIM + KVD) o[i] = bk[i - DIM];
    else if (i < NQKV) o[i] = bv[i - DIM - KVD];
}

// ---------------------------------------------------------------------------
// shared GEMM tile config
// ---------------------------------------------------------------------------
#define BM 128
#define BN 128
#define BK 64
#define NCH (DIM / BK)   // 32
#define STG_BYTES 65536
#define OFF_AH 0
#define OFF_AL 16384
#define OFF_BH 32768
#define OFF_BL 49152
#define GEMM_SMEM (2 * STG_BYTES)   // 131072

// mainloop shared by both GEMM kernels; leaves accum in d
#define GEMM_MAINLOOP(Ahg, Alg, Bhg, Blg)                                          \
    auto load_stage = [&](int s, int kt) {                                         \
        int k0 = kt * BK;                                                          \
        uint32_t base = sb + s * STG_BYTES;                                        \
        _Pragma("unroll")                                                          \
        for (int t = 0; t < 4; t++) {                                              \
            int idx = tid + t * 256;                                               \
            int r = idx >> 3, c16 = idx & 7;                                       \
            uint32_t swz = SMEM_SWIZZLE_128B((uint32_t)(r * 128 + c16 * 16));      \
            size_t ga = (size_t)(by + r) * DIM + k0 + c16 * 8;                     \
            size_t gb = (size_t)(bx + r) * DIM + k0 + c16 * 8;                     \
            cp16(base + OFF_AH + swz, Ahg + ga);                                   \
            cp16(base + OFF_AL + swz, Alg + ga);                                   \
            cp16(base + OFF_BH + swz, Bhg + gb);                                   \
            cp16(base + OFF_BL + swz, Blg + gb);                                   \
        }                                                                          \
    };                                                                             \
    float d[4][4][4];                                                              \
    _Pragma("unroll")                                                              \
    for (int i = 0; i < 4; i++)                                                    \
        _Pragma("unroll")                                                          \
        for (int j = 0; j < 4; j++)                                                \
            _Pragma("unroll")                                                      \
            for (int q = 0; q < 4; q++) d[i][j][q] = 0.f;                          \
    load_stage(0, 0);                                                              \
    CP_COMMIT();                                                                   \
    load_stage(1, 1);                                                              \
    CP_COMMIT();                                                                   \
    for (int kt = 0; kt < NCH; kt++) {                                             \
        if (kt < NCH - 1) asm volatile("cp.async.wait_group 1;" ::: "memory");     \
        else              asm volatile("cp.async.wait_group 0;" ::: "memory");     \
        __syncthreads();                                                           \
        int s = kt & 1;                                                            \
        uint32_t base = sb + s * STG_BYTES;                                        \
        int arow = wm * 64 + (lane & 15);                                          \
        int bro  = wn * 32 + (lane & 7) + ((lane >> 4) << 3);                      \
        int bkh  = ((lane >> 3) & 1) << 3;                                         \
        _Pragma("unroll")                                                          \
        for (int ks = 0; ks < 4; ks++) {                                           \
            int acol = ks * 16 + ((lane >> 4) << 3);                               \
            uint32_t ah[4][4], al[4][4], bh[4][2], bl[4][2];                       \
            _Pragma("unroll")                                                      \
            for (int mf = 0; mf < 4; mf++) {                                       \
                uint32_t off = SMEM_SWIZZLE_128B(                                  \
                    (uint32_t)((arow + mf * 16) * 128 + acol * 2));                \
                ldm4(ah[mf], base + OFF_AH + off);                                 \
                ldm4(al[mf], base + OFF_AL + off);                                 \
            }                                                                      \
            _Pragma("unroll")                                                      \
            for (int j2 = 0; j2 < 2; j2++) {                                       \
                uint32_t off = SMEM_SWIZZLE_128B(                                  \
                    (uint32_t)((bro + j2 * 16) * 128 + (ks * 16 + bkh) * 2));      \
                uint32_t r[4];                                                     \
                ldm4(r, base + OFF_BH + off);                                      \
                bh[j2 * 2][0] = r[0]; bh[j2 * 2][1] = r[1];                        \
                bh[j2 * 2 + 1][0] = r[2]; bh[j2 * 2 + 1][1] = r[3];                \
                ldm4(r, base + OFF_BL + off);                                      \
                bl[j2 * 2][0] = r[0]; bl[j2 * 2][1] = r[1];                        \
                bl[j2 * 2 + 1][0] = r[2]; bl[j2 * 2 + 1][1] = r[3];                \
            }                                                                      \
            _Pragma("unroll")                                                      \
            for (int mf = 0; mf < 4; mf++)                                         \
                _Pragma("unroll")                                                  \
                for (int nf = 0; nf < 4; nf++) {                                   \
                    mma16816(d[mf][nf], ah[mf], bh[nf]);                           \
                    mma16816(d[mf][nf], ah[mf], bl[nf]);                           \
                    mma16816(d[mf][nf], al[mf], bh[nf]);                           \
                }                                                                  \
        }                                                                          \
        __syncthreads();                                                           \
        if (kt + 2 < NCH) {                                                        \
            load_stage(s, kt + 2);                                                 \
            CP_COMMIT();                                                           \
        }                                                                          \
    }

// ---------------------------------------------------------------------------
// Fused QKV GEMM + RMSNorm + RoPE + fp16 split epilogue.
// N = 3072 concatenated [q(0..15) | k groups(16..19) | v groups(20..23)];
// each column block of 128 is exactly one head / group (hd = 128 = BN).
// Writes q/k/v operands as fp16 hi/lo in (b, head, s, hd).
// ---------------------------------------------------------------------------
__global__ __launch_bounds__(256, 1) void gemm_qkv(
    const __half* __restrict__ Ahg, const __half* __restrict__ Alg,
    const __half* __restrict__ Bhg, const __half* __restrict__ Blg,
    const float* __restrict__ bias,
    const float* __restrict__ qns, const float* __restrict__ kns,
    __half* __restrict__ qah, __half* __restrict__ qal,
    __half* __restrict__ kah, __half* __restrict__ kal,
    __half* __restrict__ vah, __half* __restrict__ val)
{
    extern __shared__ char sm[];
    uint32_t sb = smem_to_u32(sm);
    int tid = threadIdx.x, lane = tid & 31, wid = tid >> 5;
    int wm = wid & 1, wn = wid >> 1;
    int bx = blockIdx.x * BN, by = blockIdx.y * BM;

    GEMM_MAINLOOP(Ahg, Alg, Bhg, Blg)

    // ---------------- fused epilogue ----------------
    int hb = blockIdx.x;             // 0..23
    bool needs_norm = (hb < 20);     // q and k blocks

    // bias add (bias for v too; all biases are inputs)
    int c0 = wn * 32 + (lane & 3) * 2;     // hd col base (even)
    #pragma unroll
    for (int mf = 0; mf < 4; mf++)
        #pragma unroll
        for (int nf = 0; nf < 4; nf++) {
            int c = c0 + nf * 8;
            float b0 = bias[bx + c], b1 = bias[bx + c + 1];
            d[mf][nf][0] += b0; d[mf][nf][1] += b1;
            d[mf][nf][2] += b0; d[mf][nf][3] += b1;
        }

    float* ss = (float*)sm;          // [128][4] partial row sums
    __syncthreads();                 // all warps done reading smem stages

    if (needs_norm) {
        #pragma unroll
        for (int mf = 0; mf < 4; mf++) {
            float pA = 0.f, pB = 0.f;
            #pragma unroll
            for (int nf = 0; nf < 4; nf++) {
                pA += d[mf][nf][0] * d[mf][nf][0] + d[mf][nf][1] * d[mf][nf][1];
                pB += d[mf][nf][2] * d[mf][nf][2] + d[mf][nf][3] * d[mf][nf][3];
            }
            pA += __shfl_xor_sync(0xffffffffu, pA, 1);
            pA += __shfl_xor_sync(0xffffffffu, pA, 2);
            pB += __shfl_xor_sync(0xffffffffu, pB, 1);
            pB += __shfl_xor_sync(0xffffffffu, pB, 2);
            if ((lane & 3) == 0) {
                int lr = wm * 64 + mf * 16 + (lane >> 2);
                ss[lr * 4 + wn] = pA;
                ss[(lr + 8) * 4 + wn] = pB;
            }
        }
    }
    __syncthreads();

    const float* nsc = (hb < 16) ? qns : kns;
    float esc = (hb < 16) ? (1.0f / (float)HD) : 1.0f;
    __half *oph, *opl;
    int headmul;
    if (hb < 16)      { oph = qah; opl = qal; headmul = NH; }
    else if (hb < 20) { oph = kah; opl = kal; headmul = NG; }
    else              { oph = vah; opl = val; headmul = NG; }
    int head = (hb < 16) ? hb : ((hb < 20) ? hb - 16 : hb - 20);

    #pragma unroll
    for (int mf = 0; mf < 4; mf++) {
        int lr = wm * 64 + mf * 16 + (lane >> 2);
        int rowA = by + lr, rowB = rowA + 8;
        int posA = rowA & (SEQ - 1), posB = rowB & (SEQ - 1);
        int bA = rowA >> 9, bB = rowB >> 9;
        float rinvA = 1.f, rinvB = 1.f;
        if (needs_norm) {
            float sA = ss[lr * 4] + ss[lr * 4 + 1] + ss[lr * 4 + 2] + ss[lr * 4 + 3];
            float sB = ss[(lr + 8) * 4] + ss[(lr + 8) * 4 + 1] +
                       ss[(lr + 8) * 4 + 2] + ss[(lr + 8) * 4 + 3];
            rinvA = rsqrtf(sA * (1.0f / HD) + 1e-6f);
            rinvB = rsqrtf(sB * (1.0f / HD) + 1e-6f);
        }
        size_t obA = ((size_t)(bA * headmul + head) * SEQ + posA) * HD;
        size_t obB = ((size_t)(bB * headmul + head) * SEQ + posB) * HD;
        #pragma unroll
        for (int nf = 0; nf < 4; nf++) {
            int c = c0 + nf * 8;
            float oA0, oA1, oB0, oB1;
            if (needs_norm) {
                float sc0 = nsc[c], sc1 = nsc[c + 1];
                float invf = expf(-(float)(c >> 1) * (9.210340371976184f / 64.0f));
                float snA, csA, snB, csB;
                sincosf((float)posA * invf, &snA, &csA);
                sincosf((float)posB * invf, &snB, &csB);
                float xA1 = d[mf][nf][0] * rinvA * sc0;
                float xA2 = d[mf][nf][1] * rinvA * sc1;
                float xB1 = d[mf][nf][2] * rinvB * sc0;
                float xB2 = d[mf][nf][3] * rinvB * sc1;
                oA0 = (xA1 * csA - xA2 * snA) * esc;
                oA1 = (xA1 * snA + xA2 * csA) * esc;
                oB0 = (xB1 * csB - xB2 * snB) * esc;
                oB1 = (xB1 * snB + xB2 * csB) * esc;
            } else {
                oA0 = d[mf][nf][0]; oA1 = d[mf][nf][1];
                oB0 = d[mf][nf][2]; oB1 = d[mf][nf][3];
            }
            split_store(oph, opl, obA + c, oA0, oA1);
            split_store(oph, opl, obB + c, oB0, oB1);
        }
    }
}

// ---------------------------------------------------------------------------
// plain HMMA split-3 GEMM with bias, fp32 output (for Wo)
// ---------------------------------------------------------------------------
__global__ __launch_bounds__(256, 1) void gemm_hmma(
    const __half* __restrict__ Ahg, const __half* __restrict__ Alg,
    const __half* __restrict__ Bhg, const __half* __restrict__ Blg,
    const float* __restrict__ bias, float* __restrict__ C, int N)
{
    extern __shared__ char sm[];
    uint32_t sb = smem_to_u32(sm);
    int tid = threadIdx.x, lane = tid & 31, wid = tid >> 5;
    int wm = wid & 1, wn = wid >> 1;
    int bx = blockIdx.x * BN, by = blockIdx.y * BM;

    GEMM_MAINLOOP(Ahg, Alg, Bhg, Blg)

    int row0 = by + wm * 64 + (lane >> 2);
    int col0 = bx + wn * 32 + (lane & 3) * 2;
    #pragma unroll
    for (int mf = 0; mf < 4; mf++)
        #pragma unroll
        for (int nf = 0; nf < 4; nf++) {
            int r = row0 + mf * 16;
            int c = col0 + nf * 8;
            float b0 = bias[c], b1 = bias[c + 1];
            float2 v0 = make_float2(d[mf][nf][0] + b0, d[mf][nf][1] + b1);
            float2 v1 = make_float2(d[mf][nf][2] + b0, d[mf][nf][3] + b1);
            *(float2*)&C[(size_t)r * N + c] = v0;
            *(float2*)&C[(size_t)(r + 8) * N + c] = v1;
        }
}

// ---------------------------------------------------------------------------
// HMMA flash attention (unchanged from round 4)
// ---------------------------------------------------------------------------
#define FA_SMEM (196608)

__global__ __launch_bounds__(256, 1) void flash_attn_hmma(
    const __half* __restrict__ qh, const __half* __restrict__ ql,
    const __half* __restrict__ kh, const __half* __restrict__ kl,
    const __half* __restrict__ vh, const __half* __restrict__ vl,
    __half* __restrict__ aoh, __half* __restrict__ aol)
{
    extern __shared__ char sm[];
    uint32_t sb = smem_to_u32(sm);
    int qb = (gridDim.x - 1) - blockIdx.x;
    int h = blockIdx.y, b = blockIdx.z;
    int g = h >> 2;
    int tid = threadIdx.x, lane = tid & 31, wid = tid >> 5;

    const size_t qbase  = ((size_t)(b * NH + h) * SEQ + qb * 128) * HD;
    const size_t kvbase = ((size_t)(b * NG + g) * SEQ) * HD;

    const uint32_t QH = sb, QL = sb + 32768;

    auto load_q = [&]() {
        #pragma unroll
        for (int t = 0; t < 8; t++) {
            int idx = tid + t * 256;
            int r = idx >> 4, c16 = idx & 15;
            uint32_t off = (uint32_t)((c16 >> 3) * 16384) +
                           SMEM_SWIZZLE_128B((uint32_t)(r * 128 + (c16 & 7) * 16));
            size_t go = qbase + (size_t)r * HD + c16 * 8;
            cp16(QH + off, qh + go);
            cp16(QL + off, ql + go);
        }
    };
    auto load_kv = [&](int s, int kt) {
        uint32_t base = sb + 65536 + s * 65536;
        size_t kb = kvbase + (size_t)kt * 64 * HD;
        #pragma unroll
        for (int t = 0; t < 4; t++) {
            int idx = tid + t * 256;
            int r = idx >> 4, c16 = idx & 15;
            uint32_t off = (uint32_t)((c16 >> 3) * 8192) +
                           SMEM_SWIZZLE_128B((uint32_t)(r * 128 + (c16 & 7) * 16));
            size_t go = kb + (size_t)r * HD + c16 * 8;
            cp16(base + off,         kh + go);
            cp16(base + 16384 + off, kl + go);
            cp16(base + 32768 + off, vh + go);
            cp16(base + 49152 + off, vl + go);
        }
    };

    int nkt = 2 * qb + 2;
    load_q();
    load_kv(0, 0);
    CP_COMMIT();
    load_kv(1, 1);
    CP_COMMIT();

    float o[16][4];
    #pragma unroll
    for (int i = 0; i < 16; i++)
        #pragma unroll
        for (int j = 0; j < 4; j++) o[i][j] = 0.f;
    float mA = -1e30f, mB = -1e30f, lA = 0.f, lB = 0.f;

    int row0 = wid * 16;
    int sq = qb * 128 + row0;

    for (int kt = 0; kt < nkt; kt++) {
        if (kt < nkt - 1) asm volatile("cp.async.wait_group 1;" ::: "memory");
        else              asm volatile("cp.async.wait_group 0;" ::: "memory");
        __syncthreads();

        int st = kt & 1;
        uint32_t KHb = sb + 65536 + st * 65536;
        uint32_t KLb = KHb + 16384, VHb = KHb + 32768, VLb = KHb + 49152;

        bool active = (kt * 64 <= sq + 15);
        if (active) {
            float sc[8][4];
            #pragma unroll
            for (int i = 0; i < 8; i++)
                #pragma unroll
                for (int j = 0; j < 4; j++) sc[i][j] = 0.f;

            int aro  = row0 + (lane & 15);
            int kro  = (lane & 7) + ((lane >> 4) << 3);
            int bkh  = ((lane >> 3) & 1) << 3;

            #pragma unroll
            for (int ks = 0; ks < 8; ks++) {
                int chk  = ks >> 2;
                int acol = (ks & 3) * 16 + ((lane >> 4) << 3);
                uint32_t aoff = (uint32_t)(chk * 16384) +
                                SMEM_SWIZZLE_128B((uint32_t)(aro * 128 + acol * 2));
                uint32_t ah[4], al[4];
                ldm4(ah, QH + aoff);
                ldm4(al, QL + aoff);

                int bcol = (ks & 3) * 16 + bkh;
                uint32_t bh[8][2], bl[8][2];
                #pragma unroll
                for (int j2 = 0; j2 < 4; j2++) {
                    uint32_t boff = (uint32_t)(chk * 8192) +
                        SMEM_SWIZZLE_128B((uint32_t)((j2 * 16 + kro) * 128 + bcol * 2));
                    uint32_t r[4];
                    ldm4(r, KHb + boff);
                    bh[2*j2][0] = r[0]; bh[2*j2][1] = r[1];
                    bh[2*j2+1][0] = r[2]; bh[2*j2+1][1] = r[3];
                    ldm4(r, KLb + boff);
                    bl[2*j2][0] = r[0]; bl[2*j2][1] = r[1];
                    bl[2*j2+1][0] = r[2]; bl[2*j2+1][1] = r[3];
                }
                #pragma unroll
                for (int nf = 0; nf < 8; nf++) {
                    mma16816(sc[nf], ah, bh[nf]);
                    mma16816(sc[nf], ah, bl[nf]);
                    mma16816(sc[nf], al, bh[nf]);
                }
            }

            if (kt * 64 + 63 > sq) {
                int rA = sq + (lane >> 2), rB = rA + 8;
                #pragma unroll
                for (int nf = 0; nf < 8; nf++) {
                    int cbase = kt * 64 + nf * 8 + 2 * (lane & 3);
                    if (cbase     > rA) sc[nf][0] = -1e30f;
                    if (cbase + 1 > rA) sc[nf][1] = -1e30f;
                    if (cbase     > rB) sc[nf][2] = -1e30f;
                    if (cbase + 1 > rB) sc[nf][3] = -1e30f;
                }
            }

            float mtA = -1e30f, mtB = -1e30f;
            #pragma unroll
            for (int nf = 0; nf < 8; nf++) {
                mtA = fmaxf(mtA, fmaxf(sc[nf][0], sc[nf][1]));
                mtB = fmaxf(mtB, fmaxf(sc[nf][2], sc[nf][3]));
            }
            mtA = fmaxf(mtA, __shfl_xor_sync(0xffffffffu, mtA, 1));
            mtA = fmaxf(mtA, __shfl_xor_sync(0xffffffffu, mtA, 2));
            mtB = fmaxf(mtB, __shfl_xor_sync(0xffffffffu, mtB, 1));
            mtB = fmaxf(mtB, __shfl_xor_sync(0xffffffffu, mtB, 2));
            float nmA = fmaxf(mA, mtA), nmB = fmaxf(mB, mtB);
            float alA = __expf(mA - nmA), alB = __expf(mB - nmB);

            float suA = 0.f, suB = 0.f;
            #pragma unroll
            for (int nf = 0; nf < 8; nf++) {
                sc[nf][0] = __expf(sc[nf][0] - nmA); suA += sc[nf][0];
                sc[nf][1] = __expf(sc[nf][1] - nmA); suA += sc[nf][1];
                sc[nf][2] = __expf(sc[nf][2] - nmB); suB += sc[nf][2];
                sc[nf][3] = __expf(sc[nf][3] - nmB); suB += sc[nf][3];
            }
            suA += __shfl_xor_sync(0xffffffffu, suA, 1);
            suA += __shfl_xor_sync(0xffffffffu, suA, 2);
            suB += __shfl_xor_sync(0xffffffffu, suB, 1);
            suB += __shfl_xor_sync(0xffffffffu, suB, 2);
            lA = lA * alA + suA;
            lB = lB * alB + suB;
            mA = nmA; mB = nmB;
            #pragma unroll
            for (int nf = 0; nf < 16; nf++) {
                o[nf][0] *= alA; o[nf][1] *= alA;
                o[nf][2] *= alB; o[nf][3] *= alB;
            }

            int vro = (lane & 7) + (((lane >> 3) & 1) << 3);
            int vch = (lane >> 4) << 3;
            #pragma unroll
            for (int kf = 0; kf < 4; kf++) {
                uint32_t aPh[4], aPl[4];
                {
                    float p0 = sc[2*kf][0],   p1 = sc[2*kf][1];
                    float p2 = sc[2*kf][2],   p3 = sc[2*kf][3];
                    float p4 = sc[2*kf+1][0], p5 = sc[2*kf+1][1];
                    float p6 = sc[2*kf+1][2], p7 = sc[2*kf+1][3];
                    __half h0 = __float2half_rn(p0), h1 = __float2half_rn(p1);
                    __half h2 = __float2half_rn(p2), h3 = __float2half_rn(p3);
                    __half h4 = __float2half_rn(p4), h5 = __float2half_rn(p5);
                    __half h6 = __float2half_rn(p6), h7 = __float2half_rn(p7);
                    aPh[0] = pk2h(p0, p1); aPh[1] = pk2h(p2, p3);
                    aPh[2] = pk2h(p4, p5); aPh[3] = pk2h(p6, p7);
                    aPl[0] = pk2h(p0 - __half2float(h0), p1 - __half2float(h1));
                    aPl[1] = pk2h(p2 - __half2float(h2), p3 - __half2float(h3));
                    aPl[2] = pk2h(p4 - __half2float(h4), p5 - __half2float(h5));
                    aPl[3] = pk2h(p6 - __half2float(h6), p7 - __half2float(h7));
                }
                #pragma unroll
                for (int j2 = 0; j2 < 8; j2++) {
                    int chk  = j2 >> 2;
                    int wcol = (j2 & 3) * 16 + vch;
                    uint32_t voff = (uint32_t)(chk * 8192) +
                        SMEM_SWIZZLE_128B((uint32_t)((kf * 16 + vro) * 128 + wcol * 2));
                    uint32_t rh[4], rl[4];
                    ldm4t(rh, VHb + voff);
                    ldm4t(rl, VLb + voff);
                    uint32_t bh0[2] = {rh[0], rh[1]}, bh1[2] = {rh[2], rh[3]};
                    uint32_t bl0[2] = {rl[0], rl[1]}, bl1[2] = {rl[2], rl[3]};
                    mma16816(o[2*j2],   aPh, bh0);
                    mma16816(o[2*j2],   aPh, bl0);
                    mma16816(o[2*j2],   aPl, bh0);
                    mma16816(o[2*j2+1], aPh, bh1);
                    mma16816(o[2*j2+1], aPh, bl1);
                    mma16816(o[2*j2+1], aPl, bh1);
                }
            }
        }
        __syncthreads();

        if (kt + 2 < nkt) {
            load_kv(st, kt + 2);
            CP_COMMIT();
        }
    }

    float rlA = 1.0f / lA, rlB = 1.0f / lB;
    int sA = sq + (lane >> 2), sB = sA + 8;
    size_t oA = ((size_t)(b * SEQ + sA) * NH + h) * HD;
    size_t oB = ((size_t)(b * SEQ + sB) * NH + h) * HD;
    #pragma unroll
    for (int nf = 0; nf < 16; nf++) {
        int hd = nf * 8 + 2 * (lane & 3);
        float e0 = o[nf][0] * rlA, e1 = o[nf][1] * rlA;
        float e2 = o[nf][2] * rlB, e3 = o[nf][3] * rlB;
        split_store(aoh, aol, oA + hd, e0, e1);
        split_store(aoh, aol, oB + hd, e2, e3);
    }
}

// ---------------------------------------------------------------------------
extern "C" void kernel_launch(void* const* d_in, const int* in_sizes, int n_in,
                              void* d_out, int out_size)
{
    const float* x   = (const float*)d_in[0];
    const float* Wq  = (const float*)d_in[1];
    const float* bq  = (const float*)d_in[2];
    const float* Wk  = (const float*)d_in[3];
    const float* bk  = (const float*)d_in[4];
    const float* Wv  = (const float*)d_in[5];
    const float* bv  = (const float*)d_in[6];
    const float* Wo  = (const float*)d_in[7];
    const float* bo  = (const float*)d_in[8];
    const float* qns = (const float*)d_in[9];
    const float* kns = (const float*)d_in[10];
    float* out = (float*)d_out;

    __half *xhi, *xlo, *aoh, *aol, *wh, *wl, *woh, *wol;
    __half *qah, *qal, *kah, *kal, *vah, *val;
    float* bqkv;
    cudaGetSymbolAddress((void**)&xhi, g_xhi);
    cudaGetSymbolAddress((void**)&xlo, g_xlo);
    cudaGetSymbolAddress((void**)&aoh, g_aoh);
    cudaGetSymbolAddress((void**)&aol, g_aol);
    cudaGetSymbolAddress((void**)&wh,  g_wh);
    cudaGetSymbolAddress((void**)&wl,  g_wl);
    cudaGetSymbolAddress((void**)&woh, g_woh);
    cudaGetSymbolAddress((void**)&wol, g_wol);
    cudaGetSymbolAddress((void**)&bqkv, g_bqkv);
    cudaGetSymbolAddress((void**)&qah, g_qah);
    cudaGetSymbolAddress((void**)&qal, g_qal);
    cudaGetSymbolAddress((void**)&kah, g_kah);
    cudaGetSymbolAddress((void**)&kal, g_kal);
    cudaGetSymbolAddress((void**)&vah, g_vah);
    cudaGetSymbolAddress((void**)&val, g_val);

    cudaFuncSetAttribute(gemm_qkv, cudaFuncAttributeMaxDynamicSharedMemorySize, GEMM_SMEM);
    cudaFuncSetAttribute(gemm_hmma, cudaFuncAttributeMaxDynamicSharedMemorySize, GEMM_SMEM);
    cudaFuncSetAttribute(flash_attn_hmma, cudaFuncAttributeMaxDynamicSharedMemorySize, FA_SMEM);

    const int n4 = MROWS * DIM / 4;

    // conversions (weights concatenated into one [3072,2048] hi/lo buffer)
    convert_split<<<(n4 + 255) / 256, 256>>>(x, xhi, xlo, n4);
    transpose_split<<<dim3(DIM / 32, DIM / 32), dim3(32, 8)>>>(Wq, wh, wl, DIM, DIM);
    transpose_split<<<dim3(KVD / 32, DIM / 32), dim3(32, 8)>>>(
        Wk, wh + (size_t)DIM * DIM, wl + (size_t)DIM * DIM, DIM, KVD);
    transpose_split<<<dim3(KVD / 32, DIM / 32), dim3(32, 8)>>>(
        Wv, wh + (size_t)(DIM + KVD) * DIM, wl + (size_t)(DIM + KVD) * DIM, DIM, KVD);
    transpose_split<<<dim3(DIM / 32, DIM / 32), dim3(32, 8)>>>(Wo, woh, wol, DIM, DIM);
    bias_concat<<<(NQKV + 255) / 256, 256>>>(bq, bk, bv, bqkv);

    // fused QKV projection + rmsnorm + rope + split (q carries full 1/hd)
    gemm_qkv<<<dim3(NQKV / BN, MROWS / BM), 256, GEMM_SMEM>>>(
        xhi, xlo, wh, wl, bqkv, qns, kns,
        qah, qal, kah, kal, vah, val);

    // attention (HMMA)
    flash_attn_hmma<<<dim3(SEQ / 128, NH, BATCH), 256, FA_SMEM>>>(
        qah, qal, kah, kal, vah, val, aoh, aol);

    // output projection
    gemm_hmma<<<dim3(DIM / BN, MROWS / BM), 256, GEMM_SMEM>>>(
        aoh, aol, woh, wol, bo, out, DIM);
}